// round 11
// baseline (speedup 1.0000x reference)
#include <cuda_runtime.h>
#include <cuda_fp16.h>
#include <cstdint>

#define HD   2048
#define SEQ  2048
#define NB   4
#define TOK  (NB*SEQ)
#define KDIM 2048
#define BM   128
#define BN   128
#define BK   64                 // fp16 elems = 128 bytes per row
#define KITERS (KDIM/BK)        // 32
#define NTHREADS 128

typedef __half h16;

// ---------------- static device scratch (fp16 hi-only, scaled domains) --------
__device__ h16  g_xh[(size_t)TOK*HD];                             // x    s=0
__device__ h16  g_wqth[(size_t)HD*HD];                            // Wq^T s=6
__device__ h16  g_wkth[(size_t)HD*HD];                            // Wk^T s=6
__device__ h16  g_wvth[(size_t)HD*HD];                            // Wv^T s=6
__device__ h16  g_woh[(size_t)HD*HD];                             // Wo   s=6
__device__ h16  g_w1h[(size_t)HD*HD];                             // W1   s=6
__device__ h16  g_wqkth[(size_t)HD*HD];                           // (Wq^T Wk)^T s=6
__device__ h16  g_m1th[(size_t)HD*HD];                            // (Wo Wv)^T   s=6
__device__ h16  g_wvfh[(size_t)HD*HD];                            // W1WoWv s=7
__device__ h16  g_th[(size_t)TOK*HD];                             // t s=1
__device__ h16  g_uth[(size_t)TOK*HD];                            // u^T s=2
__device__ float g_sc[(size_t)NB*SEQ*SEQ];
__device__ h16  g_ph[(size_t)NB*SEQ*SEQ];                         // P s=0
__device__ float g_w2s[HD];
__device__ double g_acc;

// ---------------- helpers -----------------------------------------------------
__device__ __forceinline__ uint32_t s2u(const void* p){
    uint32_t a;
    asm("{ .reg .u64 t; cvta.to.shared.u64 t, %1; cvt.u32.u64 %0, t; }" : "=r"(a) : "l"(p));
    return a;
}
__device__ __forceinline__ uint32_t pkh(h16 a, h16 b){
    __half2 t(a, b); return *reinterpret_cast<uint32_t*>(&t);
}

#define CPA(dst, src) asm volatile("cp.async.cg.shared.global [%0], [%1], 16;" \
    :: "r"(dst), "l"(src) : "memory")
#define CPA_COMMIT() asm volatile("cp.async.commit_group;" ::: "memory")

__device__ __forceinline__ void ldm4(uint32_t* r, uint32_t addr){
    asm volatile("ldmatrix.sync.aligned.m8n8.x4.shared.b16 {%0,%1,%2,%3}, [%4];"
        : "=r"(r[0]), "=r"(r[1]), "=r"(r[2]), "=r"(r[3]) : "r"(addr));
}
__device__ __forceinline__ void mma_f16(float* d, const uint32_t* a, const uint32_t* b){
    asm volatile(
        "mma.sync.aligned.m16n8k16.row.col.f32.f16.f16.f32 "
        "{%0,%1,%2,%3}, {%4,%5,%6,%7}, {%8,%9}, {%0,%1,%2,%3};"
        : "+f"(d[0]), "+f"(d[1]), "+f"(d[2]), "+f"(d[3])
        : "r"(a[0]), "r"(a[1]), "r"(a[2]), "r"(a[3]), "r"(b[0]), "r"(b[1]));
}

#define TILE_B   16384
#define STAGE_B  32768
#define NSTAGE   3
#define SMEM_TOT (NSTAGE*STAGE_B)    // 96KB -> 2 CTAs/SM

// ---------------- 1-term fp16 mma.sync GEMM ------------------------------------
// C[m,n] = oscale * sum_k A[m,k]*B[n,k]  (NT), K=2048, leading dims 2048.
// 128 threads, 2x2 warps of 64x64 tiles (B fragments streamed).
// MODE 0: write fp16 Ch ; 1: fp32 Cf ; 2: sum(relu(C)*w2s) -> g_acc
template<int MODE>
__global__ void __launch_bounds__(NTHREADS, 2) mma_gemm(
    const h16* __restrict__ Ah, const h16* __restrict__ Bh,
    h16* __restrict__ Ch, float* __restrict__ Cf,
    const float* __restrict__ w2s, float oscale,
    size_t sA, size_t sB, size_t sC)
{
    extern __shared__ char smem[];
    const uint32_t sb = s2u(smem);

    const int tid = threadIdx.x;
    const int l   = tid & 31;
    const int wid = tid >> 5;         // 0..3
    const int wm  = wid & 1;          // 2 warps along M (64 rows each)
    const int wn  = wid >> 1;         // 2 warps along N (64 cols each)
    const int bn  = blockIdx.x * BN;
    const int bm  = blockIdx.y * BM;
    const size_t zo = blockIdx.z;

    Ah += zo * sA;  Bh += zo * sB;

    // ---- producer (cp.async) addressing: 128 threads cover 16 rows x 128B
    const int pr = tid >> 3;                 // 0..15 base row
    const int pc = (tid & 7) * 16;           // byte col in 128B row
    const uint32_t pdst = (uint32_t)pr * 128u + ((uint32_t)pc ^ (((uint32_t)pr & 7u) << 4));
    const char* gAh = (const char*)(Ah + (size_t)(bm + pr) * KDIM) + pc;
    const char* gBh = (const char*)(Bh + (size_t)(bn + pr) * KDIM) + pc;

    // ---- consumer (ldmatrix) addressing
    const int ar    = wm * 64 + (l & 15);
    const int akoff = (l >> 4) * 16;
    const uint32_t xA = ((uint32_t)ar & 7u) << 4;
    const int br    = wn * 64 + (l & 7) + ((l >> 4) & 1) * 8;   // + p*16
    const int bkoff = ((l >> 3) & 1) * 16;
    const uint32_t xB = ((uint32_t)br & 7u) << 4;

    float acc[4][8][4];
    #pragma unroll
    for (int i = 0; i < 4; i++)
        #pragma unroll
        for (int j = 0; j < 8; j++)
            #pragma unroll
            for (int r = 0; r < 4; r++) acc[i][j][r] = 0.f;

    // ---- prologue: chunks 0,1 into bufs 0,1 (8 row-strides of 16 rows each)
    #pragma unroll
    for (int s = 0; s < NSTAGE - 1; s++){
        const uint32_t s0 = sb + (uint32_t)s * STAGE_B;
        const size_t ko = (size_t)s * 128;
        #pragma unroll
        for (int j = 0; j < 8; j++){
            const size_t go = (size_t)j * 65536 + ko;     // +16 rows
            CPA(s0 +          pdst + j*2048, gAh + go);
            CPA(s0 + TILE_B + pdst + j*2048, gBh + go);
        }
        CPA_COMMIT();
    }

    int bufc = 0;
    int bufp = NSTAGE - 1;
    #pragma unroll 1
    for (int i = 0; i < KITERS; i++){
        asm volatile("cp.async.wait_group 1;" ::: "memory");
        __syncthreads();

        // produce chunk i+2 into the just-freed buffer (after sync => safe)
        if (i + NSTAGE - 1 < KITERS){
            const uint32_t s0 = sb + (uint32_t)bufp * STAGE_B;
            const size_t ko = (size_t)(i + NSTAGE - 1) * 128;
            #pragma unroll
            for (int j = 0; j < 8; j++){
                const size_t go = (size_t)j * 65536 + ko;
                CPA(s0 +          pdst + j*2048, gAh + go);
                CPA(s0 + TILE_B + pdst + j*2048, gBh + go);
            }
        }
        CPA_COMMIT();   // always commit to keep group counting aligned

        const uint32_t s0 = sb + (uint32_t)bufc * STAGE_B;
        #pragma unroll
        for (int ks = 0; ks < 4; ks++){
            const uint32_t kb = (uint32_t)ks * 32;
            uint32_t ah[4][4];
            #pragma unroll
            for (int fm = 0; fm < 4; fm++){
                uint32_t ad = s0 + (uint32_t)(ar + fm*16) * 128u + ((kb + akoff) ^ xA);
                ldm4(ah[fm], ad);
            }
            #pragma unroll
            for (int p = 0; p < 4; p++){          // stream B: 16 N-rows -> 2 fn
                uint32_t bh[4];
                uint32_t bd = s0 + TILE_B + (uint32_t)(br + p*16) * 128u + ((kb + bkoff) ^ xB);
                ldm4(bh, bd);
                #pragma unroll
                for (int fm = 0; fm < 4; fm++){
                    mma_f16(acc[fm][2*p + 0], ah[fm], &bh[0]);
                    mma_f16(acc[fm][2*p + 1], ah[fm], &bh[2]);
                }
            }
        }

        bufc = (bufc + 1 == NSTAGE) ? 0 : bufc + 1;
        bufp = (bufp + 1 == NSTAGE) ? 0 : bufp + 1;
    }

    // ---- epilogue
    const int crow = l >> 2;
    const int ccol = (l & 3) * 2;
    double local = 0.0;

    #pragma unroll
    for (int fm = 0; fm < 4; fm++){
        #pragma unroll
        for (int fn = 0; fn < 8; fn++){
            const int m0 = bm + wm*64 + fm*16 + crow;
            const int n0 = bn + wn*64 + fn*8 + ccol;
            const float* c = acc[fm][fn];
            if (MODE == 1){
                float* base = Cf + zo*sC;
                *(float2*)(base + (size_t)m0 * KDIM + n0)
                    = make_float2(c[0]*oscale, c[1]*oscale);
                *(float2*)(base + (size_t)(m0+8) * KDIM + n0)
                    = make_float2(c[2]*oscale, c[3]*oscale);
            } else if (MODE == 0){
                const size_t o0 = zo*sC + (size_t)m0 * KDIM + n0;
                const size_t o1 = zo*sC + (size_t)(m0+8) * KDIM + n0;
                *(uint32_t*)(Ch + o0) = pkh(__float2half_rn(c[0]*oscale),
                                            __float2half_rn(c[1]*oscale));
                *(uint32_t*)(Ch + o1) = pkh(__float2half_rn(c[2]*oscale),
                                            __float2half_rn(c[3]*oscale));
            } else {
                float w0 = w2s[n0], w1 = w2s[n0+1];
                float z;
                z = c[0]*oscale; local += (double)((z > 0.f ? z : 0.f) * w0);
                z = c[1]*oscale; local += (double)((z > 0.f ? z : 0.f) * w1);
                z = c[2]*oscale; local += (double)((z > 0.f ? z : 0.f) * w0);
                z = c[3]*oscale; local += (double)((z > 0.f ? z : 0.f) * w1);
            }
        }
    }

    if (MODE == 2){
        __syncthreads();
        double* red = (double*)smem;
        red[tid] = local;
        __syncthreads();
        #pragma unroll
        for (int s = 64; s > 0; s >>= 1){
            if (tid < s) red[tid] += red[tid + s];
            __syncthreads();
        }
        if (tid == 0) atomicAdd(&g_acc, red[0]);
    }
}

// ---------------- aux kernels -------------------------------------------------
__global__ void chalf_k(const float4* __restrict__ in, uint2* __restrict__ oh,
                        float scale)
{
    size_t i = (size_t)blockIdx.x * 256 + threadIdx.x;
    float4 f = in[i];
    oh[i] = make_uint2(pkh(__float2half_rn(f.x*scale), __float2half_rn(f.y*scale)),
                       pkh(__float2half_rn(f.z*scale), __float2half_rn(f.w*scale)));
}

// out[C][R] = in[R][C] * scale (fp16 hi); grid (C/32, R/32), block (32,8)
__global__ void thalf_k(const float* __restrict__ in, h16* __restrict__ oh,
                        int R, int C, float scale)
{
    __shared__ float t[32][33];
    int c0 = blockIdx.x * 32, r0 = blockIdx.y * 32;
    int tx = threadIdx.x, ty = threadIdx.y;
    #pragma unroll
    for (int j = 0; j < 32; j += 8)
        t[ty + j][tx] = in[(size_t)(r0 + ty + j) * C + c0 + tx];
    __syncthreads();
    #pragma unroll
    for (int j = 0; j < 32; j += 8){
        size_t o = (size_t)(c0 + ty + j) * R + r0 + tx;
        oh[o] = __float2half_rn(t[tx][ty + j] * scale);
    }
}

__global__ void softmax_k(const float* __restrict__ S, h16* __restrict__ Ph)
{
    const float* row = S + (size_t)blockIdx.x * SEQ;
    h16* ph = Ph + (size_t)blockIdx.x * SEQ;
    const int tid = threadIdx.x;  // 256
    __shared__ float sm[256];

    float v[8];
    float mx = -3.0e38f;
    #pragma unroll
    for (int t = 0; t < 8; t++){ v[t] = row[tid + 256*t]; mx = fmaxf(mx, v[t]); }
    sm[tid] = mx; __syncthreads();
    #pragma unroll
    for (int s = 128; s > 0; s >>= 1){
        if (tid < s) sm[tid] = fmaxf(sm[tid], sm[tid + s]);
        __syncthreads();
    }
    mx = sm[0]; __syncthreads();

    float sum = 0.f;
    #pragma unroll
    for (int t = 0; t < 8; t++){ v[t] = expf(v[t] - mx); sum += v[t]; }
    sm[tid] = sum; __syncthreads();
    #pragma unroll
    for (int s = 128; s > 0; s >>= 1){
        if (tid < s) sm[tid] += sm[tid + s];
        __syncthreads();
    }
    float inv = 1.0f / sm[0];
    #pragma unroll
    for (int t = 0; t < 8; t++)
        ph[tid + 256*t] = __float2half_rn(v[t] * inv);
}

__global__ void w2sum_k(const float* __restrict__ W2)
{
    int e = blockIdx.x * 256 + threadIdx.x;
    if (e == 0) g_acc = 0.0;
    float s = 0.f;
    for (int d = 0; d < HD; d++) s += W2[(size_t)d * HD + e];
    g_w2s[e] = s;
}

__global__ void out_k(float* __restrict__ out){ out[0] = (float)g_acc; }

// ---------------- launch --------------------------------------------------------
extern "C" void kernel_launch(void* const* d_in, const int* in_sizes, int n_in,
                              void* d_out, int out_size)
{
    const float* x  = (const float*)d_in[0];
    const float* Wq = (const float*)d_in[1];
    const float* Wk = (const float*)d_in[2];
    const float* Wv = (const float*)d_in[3];
    const float* Wo = (const float*)d_in[4];
    const float* W1 = (const float*)d_in[5];
    const float* W2 = (const float*)d_in[6];

    cudaFuncSetAttribute(mma_gemm<0>, cudaFuncAttributeMaxDynamicSharedMemorySize, SMEM_TOT);
    cudaFuncSetAttribute(mma_gemm<1>, cudaFuncAttributeMaxDynamicSharedMemorySize, SMEM_TOT);
    cudaFuncSetAttribute(mma_gemm<2>, cudaFuncAttributeMaxDynamicSharedMemorySize, SMEM_TOT);

    h16 *xh,*wqth,*wkth,*wvth,*woh,*w1h,*wqkth,*m1th,*wvfh,*th,*uth,*ph;
    float *sc,*w2s;
    cudaGetSymbolAddress((void**)&xh, g_xh);
    cudaGetSymbolAddress((void**)&wqth, g_wqth);
    cudaGetSymbolAddress((void**)&wkth, g_wkth);
    cudaGetSymbolAddress((void**)&wvth, g_wvth);
    cudaGetSymbolAddress((void**)&woh, g_woh);
    cudaGetSymbolAddress((void**)&w1h, g_w1h);
    cudaGetSymbolAddress((void**)&wqkth, g_wqkth);
    cudaGetSymbolAddress((void**)&m1th, g_m1th);
    cudaGetSymbolAddress((void**)&wvfh, g_wvfh);
    cudaGetSymbolAddress((void**)&th, g_th);
    cudaGetSymbolAddress((void**)&uth, g_uth);
    cudaGetSymbolAddress((void**)&ph, g_ph);
    cudaGetSymbolAddress((void**)&sc, g_sc);
    cudaGetSymbolAddress((void**)&w2s, g_w2s);

    const size_t SH = (size_t)SEQ * HD;
    const size_t SS = (size_t)SEQ * SEQ;
    const float WS = 64.0f;           // weight pre-scale 2^6
    dim3 t8(32, 8);
    dim3 gW(HD/BN, HD/BM, 1);

    w2sum_k<<<HD/256, 256>>>(W2);

    // inputs -> fp16 hi-only (scaled)
    chalf_k<<<(int)((size_t)TOK*HD/1024), 256>>>((const float4*)x,  (uint2*)xh, 1.0f);
    chalf_k<<<HD*HD/1024, 256>>>((const float4*)Wo, (uint2*)woh, WS);
    chalf_k<<<HD*HD/1024, 256>>>((const float4*)W1, (uint2*)w1h, WS);
    thalf_k<<<dim3(HD/32, HD/32, 1), t8>>>(Wq, wqth, HD, HD, WS);
    thalf_k<<<dim3(HD/32, HD/32, 1), t8>>>(Wk, wkth, HD, HD, WS);
    thalf_k<<<dim3(HD/32, HD/32, 1), t8>>>(Wv, wvth, HD, HD, WS);

    // -------- score path: score = x (Wq^T Wk) x^T --------
    // Wqkt = NT(Wk^T, Wq^T); store s=6: os=2^(6-12)
    mma_gemm<0><<<gW, NTHREADS, SMEM_TOT>>>(wkth, wqth, wqkth, nullptr, nullptr,
                                            0.015625f, 0,0,0);
    // t = NT(x, Wqkt); store s=1: os=2^(1-0-6)
    dim3 gT(HD/BN, TOK/BM, 1);
    mma_gemm<0><<<gT, NTHREADS, SMEM_TOT>>>(xh, wqkth, th, nullptr, nullptr,
                                            0.03125f, 0,0,0);
    // score[b] = NT(t[b], x[b]) fp32; os=2^(0-1-0)
    dim3 gSc(SEQ/BN, SEQ/BM, NB);
    mma_gemm<1><<<gSc, NTHREADS, SMEM_TOT>>>(th, xh, nullptr, sc, nullptr,
                                             0.5f, SH, SH, SS);

    softmax_k<<<NB*SEQ, 256>>>(sc, ph);

    // -------- value path: Z = P (x Wvf^T), Wvf = W1 Wo Wv --------
    // M1t = NT(Wv^T, Wo); store s=6: os=2^(6-12)
    mma_gemm<0><<<gW, NTHREADS, SMEM_TOT>>>(wvth, woh, m1th, nullptr, nullptr,
                                            0.015625f, 0,0,0);
    // Wvf = NT(W1, M1t); store s=7: os=2^(7-12)
    mma_gemm<0><<<gW, NTHREADS, SMEM_TOT>>>(w1h, m1th, wvfh, nullptr, nullptr,
                                            0.03125f, 0,0,0);
    // uT[b] = NT(Wvf, x[b]); store s=2: os=2^(2-7)
    dim3 gU(SEQ/BN, HD/BM, NB);
    mma_gemm<0><<<gU, NTHREADS, SMEM_TOT>>>(wvfh, xh, uth, nullptr, nullptr,
                                            0.03125f, 0, SH, SH);
    // Z[b] = NT(P[b], uT[b]) reduce; os=2^(0-0-2)
    dim3 gZ(HD/BN, SEQ/BM, NB);
    mma_gemm<2><<<gZ, NTHREADS, SMEM_TOT>>>(ph, uth, nullptr, nullptr, w2s,
                                            0.25f, SS, SH, 0);

    out_k<<<1,1>>>((float*)d_out);
}

// round 12
// speedup vs baseline: 1.0253x; 1.0253x over previous
#include <cuda_runtime.h>
#include <cuda_fp16.h>
#include <cstdint>

#define HD   2048
#define SEQ  2048
#define NB   4
#define TOK  (NB*SEQ)
#define KDIM 2048
#define BM   128
#define BN   128
#define BK   64                 // fp16 elems = 128 bytes per row
#define KITERS (KDIM/BK)        // 32
#define NTHREADS 128

typedef __half h16;

// ---------------- static device scratch (fp16 hi-only, scaled domains) --------
__device__ h16  g_xh[(size_t)TOK*HD];                             // x    s=0
__device__ h16  g_wqth[(size_t)HD*HD];                            // Wq^T s=6
__device__ h16  g_wkth[(size_t)HD*HD];                            // Wk^T s=6
__device__ h16  g_wvth[(size_t)HD*HD];                            // Wv^T s=6
__device__ h16  g_woh[(size_t)HD*HD];                             // Wo   s=6
__device__ h16  g_w1h[(size_t)HD*HD];                             // W1   s=6
__device__ h16  g_wqkth[(size_t)HD*HD];                           // (Wq^T Wk)^T s=6
__device__ h16  g_m1th[(size_t)HD*HD];                            // (Wo Wv)^T   s=6
__device__ h16  g_wvfh[(size_t)HD*HD];                            // W1WoWv s=7
__device__ h16  g_th[(size_t)TOK*HD];                             // t s=1
__device__ h16  g_uth[(size_t)TOK*HD];                            // u^T s=2
__device__ float g_sc[(size_t)NB*SEQ*SEQ];
__device__ h16  g_ph[(size_t)NB*SEQ*SEQ];                         // P s=0
__device__ float g_w2s[HD];
__device__ double g_acc;

// ---------------- helpers -----------------------------------------------------
__device__ __forceinline__ uint32_t s2u(const void* p){
    uint32_t a;
    asm("{ .reg .u64 t; cvta.to.shared.u64 t, %1; cvt.u32.u64 %0, t; }" : "=r"(a) : "l"(p));
    return a;
}
__device__ __forceinline__ uint32_t pkh(h16 a, h16 b){
    __half2 t(a, b); return *reinterpret_cast<uint32_t*>(&t);
}

#define CPA(dst, src) asm volatile("cp.async.cg.shared.global [%0], [%1], 16;" \
    :: "r"(dst), "l"(src) : "memory")
#define CPA_COMMIT() asm volatile("cp.async.commit_group;" ::: "memory")

__device__ __forceinline__ void ldm4(uint32_t* r, uint32_t addr){
    asm volatile("ldmatrix.sync.aligned.m8n8.x4.shared.b16 {%0,%1,%2,%3}, [%4];"
        : "=r"(r[0]), "=r"(r[1]), "=r"(r[2]), "=r"(r[3]) : "r"(addr));
}
__device__ __forceinline__ void mma_f16(float* d, const uint32_t* a, const uint32_t* b){
    asm volatile(
        "mma.sync.aligned.m16n8k16.row.col.f32.f16.f16.f32 "
        "{%0,%1,%2,%3}, {%4,%5,%6,%7}, {%8,%9}, {%0,%1,%2,%3};"
        : "+f"(d[0]), "+f"(d[1]), "+f"(d[2]), "+f"(d[3])
        : "r"(a[0]), "r"(a[1]), "r"(a[2]), "r"(a[3]), "r"(b[0]), "r"(b[1]));
}

#define TILE_B   16384
#define STAGE_B  32768
#define NSTAGE   3
#define SMEM_TOT (NSTAGE*STAGE_B)    // 96KB -> 2 CTAs/SM

// ---------------- 1-term fp16 GEMM device body ---------------------------------
// C[m,n] = oscale * sum_k A[m,k]*B[n,k]  (NT), K=2048, leading dims 2048.
// 128 threads, 2x2 warps of 64x64 tiles. Caller pre-offsets pointers per batch.
// MODE 0: write fp16 Ch ; 1: fp32 Cf ; 2: sum(relu(C)*w2s) -> g_acc
template<int MODE>
__device__ __forceinline__ void gemm_body(
    const h16* __restrict__ Ah, const h16* __restrict__ Bh,
    h16* __restrict__ Ch, float* __restrict__ Cf,
    const float* __restrict__ w2s, float oscale,
    int bm, int bn, char* smem)
{
    const uint32_t sb = s2u(smem);

    const int tid = threadIdx.x;
    const int l   = tid & 31;
    const int wid = tid >> 5;         // 0..3
    const int wm  = wid & 1;          // 2 warps along M (64 rows each)
    const int wn  = wid >> 1;         // 2 warps along N (64 cols each)

    // ---- producer (cp.async) addressing: 128 threads cover 16 rows x 128B
    const int pr = tid >> 3;                 // 0..15 base row
    const int pc = (tid & 7) * 16;           // byte col in 128B row
    const uint32_t pdst = (uint32_t)pr * 128u + ((uint32_t)pc ^ (((uint32_t)pr & 7u) << 4));
    const char* gAh = (const char*)(Ah + (size_t)(bm + pr) * KDIM) + pc;
    const char* gBh = (const char*)(Bh + (size_t)(bn + pr) * KDIM) + pc;

    // ---- consumer (ldmatrix) addressing
    const int ar    = wm * 64 + (l & 15);
    const int akoff = (l >> 4) * 16;
    const uint32_t xA = ((uint32_t)ar & 7u) << 4;
    const int br    = wn * 64 + (l & 7) + ((l >> 4) & 1) * 8;   // + p*16
    const int bkoff = ((l >> 3) & 1) * 16;
    const uint32_t xB = ((uint32_t)br & 7u) << 4;

    float acc[4][8][4];
    #pragma unroll
    for (int i = 0; i < 4; i++)
        #pragma unroll
        for (int j = 0; j < 8; j++)
            #pragma unroll
            for (int r = 0; r < 4; r++) acc[i][j][r] = 0.f;

    // ---- prologue: chunks 0,1 into bufs 0,1 (8 row-strides of 16 rows each)
    #pragma unroll
    for (int s = 0; s < NSTAGE - 1; s++){
        const uint32_t s0 = sb + (uint32_t)s * STAGE_B;
        const size_t ko = (size_t)s * 128;
        #pragma unroll
        for (int j = 0; j < 8; j++){
            const size_t go = (size_t)j * 65536 + ko;     // +16 rows
            CPA(s0 +          pdst + j*2048, gAh + go);
            CPA(s0 + TILE_B + pdst + j*2048, gBh + go);
        }
        CPA_COMMIT();
    }

    int bufc = 0;
    int bufp = NSTAGE - 1;
    #pragma unroll 1
    for (int i = 0; i < KITERS; i++){
        asm volatile("cp.async.wait_group 1;" ::: "memory");
        __syncthreads();

        // produce chunk i+2 into the just-freed buffer (after sync => safe)
        if (i + NSTAGE - 1 < KITERS){
            const uint32_t s0 = sb + (uint32_t)bufp * STAGE_B;
            const size_t ko = (size_t)(i + NSTAGE - 1) * 128;
            #pragma unroll
            for (int j = 0; j < 8; j++){
                const size_t go = (size_t)j * 65536 + ko;
                CPA(s0 +          pdst + j*2048, gAh + go);
                CPA(s0 + TILE_B + pdst + j*2048, gBh + go);
            }
        }
        CPA_COMMIT();   // always commit to keep group counting aligned

        const uint32_t s0 = sb + (uint32_t)bufc * STAGE_B;
        #pragma unroll
        for (int ks = 0; ks < 4; ks++){
            const uint32_t kb = (uint32_t)ks * 32;
            uint32_t ah[4][4];
            #pragma unroll
            for (int fm = 0; fm < 4; fm++){
                uint32_t ad = s0 + (uint32_t)(ar + fm*16) * 128u + ((kb + akoff) ^ xA);
                ldm4(ah[fm], ad);
            }
            #pragma unroll
            for (int p = 0; p < 4; p++){          // stream B: 16 N-rows -> 2 fn
                uint32_t bh[4];
                uint32_t bd = s0 + TILE_B + (uint32_t)(br + p*16) * 128u + ((kb + bkoff) ^ xB);
                ldm4(bh, bd);
                #pragma unroll
                for (int fm = 0; fm < 4; fm++){
                    mma_f16(acc[fm][2*p + 0], ah[fm], &bh[0]);
                    mma_f16(acc[fm][2*p + 1], ah[fm], &bh[2]);
                }
            }
        }

        bufc = (bufc + 1 == NSTAGE) ? 0 : bufc + 1;
        bufp = (bufp + 1 == NSTAGE) ? 0 : bufp + 1;
    }

    // ---- epilogue
    const int crow = l >> 2;
    const int ccol = (l & 3) * 2;
    double local = 0.0;

    #pragma unroll
    for (int fm = 0; fm < 4; fm++){
        #pragma unroll
        for (int fn = 0; fn < 8; fn++){
            const int m0 = bm + wm*64 + fm*16 + crow;
            const int n0 = bn + wn*64 + fn*8 + ccol;
            const float* c = acc[fm][fn];
            if (MODE == 1){
                *(float2*)(Cf + (size_t)m0 * KDIM + n0)
                    = make_float2(c[0]*oscale, c[1]*oscale);
                *(float2*)(Cf + (size_t)(m0+8) * KDIM + n0)
                    = make_float2(c[2]*oscale, c[3]*oscale);
            } else if (MODE == 0){
                const size_t o0 = (size_t)m0 * KDIM + n0;
                const size_t o1 = (size_t)(m0+8) * KDIM + n0;
                *(uint32_t*)(Ch + o0) = pkh(__float2half_rn(c[0]*oscale),
                                            __float2half_rn(c[1]*oscale));
                *(uint32_t*)(Ch + o1) = pkh(__float2half_rn(c[2]*oscale),
                                            __float2half_rn(c[3]*oscale));
            } else {
                float w0 = w2s[n0], w1 = w2s[n0+1];
                float z;
                z = c[0]*oscale; local += (double)((z > 0.f ? z : 0.f) * w0);
                z = c[1]*oscale; local += (double)((z > 0.f ? z : 0.f) * w1);
                z = c[2]*oscale; local += (double)((z > 0.f ? z : 0.f) * w0);
                z = c[3]*oscale; local += (double)((z > 0.f ? z : 0.f) * w1);
            }
        }
    }

    if (MODE == 2){
        __syncthreads();
        double* red = (double*)smem;
        red[tid] = local;
        __syncthreads();
        #pragma unroll
        for (int s = 64; s > 0; s >>= 1){
            if (tid < s) red[tid] += red[tid + s];
            __syncthreads();
        }
        if (tid == 0) atomicAdd(&g_acc, red[0]);
    }
}

// ---------------- GEMM kernels --------------------------------------------------
// generic batched (z) GEMM
template<int MODE>
__global__ void __launch_bounds__(NTHREADS, 2) mma_one(
    const h16* __restrict__ Ah, const h16* __restrict__ Bh,
    h16* __restrict__ Ch, float* __restrict__ Cf,
    const float* __restrict__ w2s, float oscale,
    size_t sA, size_t sB, size_t sC)
{
    extern __shared__ char smem[];
    const size_t zo = blockIdx.z;
    gemm_body<MODE>(Ah + zo*sA, Bh + zo*sB,
                    (MODE == 0) ? Ch + zo*sC : nullptr,
                    (MODE == 1) ? Cf + zo*sC : nullptr,
                    w2s, oscale, blockIdx.y * BM, blockIdx.x * BN, smem);
}

// merged: z=0 -> Wqkt = NT(Wk^T, Wq^T) os 2^-6 ; z=1 -> Wvf = NT(W1, M1t) os 2^-5
__global__ void __launch_bounds__(NTHREADS, 2) k_wqkt_wvf(
    const h16* __restrict__ wkth, const h16* __restrict__ wqth, h16* __restrict__ wqkth,
    const h16* __restrict__ w1h,  const h16* __restrict__ m1th, h16* __restrict__ wvfh)
{
    extern __shared__ char smem[];
    const h16 *A, *B; h16* C; float os;
    if (blockIdx.z == 0){ A = wkth; B = wqth; C = wqkth; os = 0.015625f; }
    else                { A = w1h;  B = m1th; C = wvfh;  os = 0.03125f;  }
    gemm_body<0>(A, B, C, nullptr, nullptr, os, blockIdx.y * BM, blockIdx.x * BN, smem);
}

// merged: y<64 -> t = NT(x, Wqkt) ; y>=64 -> uT[b] = NT(Wvf, x[b]) ; both os 2^-5
__global__ void __launch_bounds__(NTHREADS, 2) k_t_ut(
    const h16* __restrict__ xh, const h16* __restrict__ wqkth, h16* __restrict__ th,
    const h16* __restrict__ wvfh, h16* __restrict__ uth)
{
    extern __shared__ char smem[];
    const size_t SH = (size_t)SEQ * HD;
    const int y = blockIdx.y;
    const h16 *A, *B; h16* C; int bm;
    if (y < 64){            // t
        A = xh;  B = wqkth;  C = th;  bm = y * BM;
    } else {                // uT, batch b
        const int yy = y - 64;
        const int b  = yy >> 4;
        A = wvfh;  B = xh + (size_t)b * SH;  C = uth + (size_t)b * SH;
        bm = (yy & 15) * BM;
    }
    gemm_body<0>(A, B, C, nullptr, nullptr, 0.03125f, bm, blockIdx.x * BN, smem);
}

// ---------------- aux kernels -------------------------------------------------
__global__ void chalf_k(const float4* __restrict__ in, uint2* __restrict__ oh,
                        float scale)
{
    size_t i = (size_t)blockIdx.x * 256 + threadIdx.x;
    float4 f = in[i];
    oh[i] = make_uint2(pkh(__float2half_rn(f.x*scale), __float2half_rn(f.y*scale)),
                       pkh(__float2half_rn(f.z*scale), __float2half_rn(f.w*scale)));
}

// merged weight chalf: z selects (Wo, W1)
__global__ void chalf2_k(const float4* __restrict__ w0, uint2* __restrict__ o0,
                         const float4* __restrict__ w1, uint2* __restrict__ o1,
                         float scale)
{
    size_t i = (size_t)blockIdx.x * 256 + threadIdx.x;
    const float4* in = (blockIdx.z == 0) ? w0 : w1;
    uint2* oh        = (blockIdx.z == 0) ? o0 : o1;
    float4 f = in[i];
    oh[i] = make_uint2(pkh(__float2half_rn(f.x*scale), __float2half_rn(f.y*scale)),
                       pkh(__float2half_rn(f.z*scale), __float2half_rn(f.w*scale)));
}

// merged transpose: out[C][R] = in[R][C] * scale ; z selects (Wq, Wk, Wv)
__global__ void thalf3_k(const float* __restrict__ i0, h16* __restrict__ o0,
                         const float* __restrict__ i1, h16* __restrict__ o1,
                         const float* __restrict__ i2, h16* __restrict__ o2,
                         float scale)
{
    __shared__ float t[32][33];
    const float* in = (blockIdx.z == 0) ? i0 : (blockIdx.z == 1) ? i1 : i2;
    h16* oh         = (blockIdx.z == 0) ? o0 : (blockIdx.z == 1) ? o1 : o2;
    int c0 = blockIdx.x * 32, r0 = blockIdx.y * 32;
    int tx = threadIdx.x, ty = threadIdx.y;
    #pragma unroll
    for (int j = 0; j < 32; j += 8)
        t[ty + j][tx] = in[(size_t)(r0 + ty + j) * HD + c0 + tx];
    __syncthreads();
    #pragma unroll
    for (int j = 0; j < 32; j += 8){
        size_t o = (size_t)(c0 + ty + j) * HD + r0 + tx;
        oh[o] = __float2half_rn(t[tx][ty + j] * scale);
    }
}

__global__ void softmax_k(const float* __restrict__ S, h16* __restrict__ Ph)
{
    const float* row = S + (size_t)blockIdx.x * SEQ;
    h16* ph = Ph + (size_t)blockIdx.x * SEQ;
    const int tid = threadIdx.x;  // 256
    __shared__ float sm[256];

    float v[8];
    float mx = -3.0e38f;
    #pragma unroll
    for (int t = 0; t < 8; t++){ v[t] = row[tid + 256*t]; mx = fmaxf(mx, v[t]); }
    sm[tid] = mx; __syncthreads();
    #pragma unroll
    for (int s = 128; s > 0; s >>= 1){
        if (tid < s) sm[tid] = fmaxf(sm[tid], sm[tid + s]);
        __syncthreads();
    }
    mx = sm[0]; __syncthreads();

    float sum = 0.f;
    #pragma unroll
    for (int t = 0; t < 8; t++){ v[t] = expf(v[t] - mx); sum += v[t]; }
    sm[tid] = sum; __syncthreads();
    #pragma unroll
    for (int s = 128; s > 0; s >>= 1){
        if (tid < s) sm[tid] += sm[tid + s];
        __syncthreads();
    }
    float inv = 1.0f / sm[0];
    #pragma unroll
    for (int t = 0; t < 8; t++)
        ph[tid + 256*t] = __float2half_rn(v[t] * inv);
}

__global__ void w2sum_k(const float* __restrict__ W2)
{
    int e = blockIdx.x * 256 + threadIdx.x;
    if (e == 0) g_acc = 0.0;
    float s = 0.f;
    for (int d = 0; d < HD; d++) s += W2[(size_t)d * HD + e];
    g_w2s[e] = s;
}

__global__ void out_k(float* __restrict__ out){ out[0] = (float)g_acc; }

// ---------------- launch --------------------------------------------------------
extern "C" void kernel_launch(void* const* d_in, const int* in_sizes, int n_in,
                              void* d_out, int out_size)
{
    const float* x  = (const float*)d_in[0];
    const float* Wq = (const float*)d_in[1];
    const float* Wk = (const float*)d_in[2];
    const float* Wv = (const float*)d_in[3];
    const float* Wo = (const float*)d_in[4];
    const float* W1 = (const float*)d_in[5];
    const float* W2 = (const float*)d_in[6];

    cudaFuncSetAttribute(mma_one<0>, cudaFuncAttributeMaxDynamicSharedMemorySize, SMEM_TOT);
    cudaFuncSetAttribute(mma_one<1>, cudaFuncAttributeMaxDynamicSharedMemorySize, SMEM_TOT);
    cudaFuncSetAttribute(mma_one<2>, cudaFuncAttributeMaxDynamicSharedMemorySize, SMEM_TOT);
    cudaFuncSetAttribute(k_wqkt_wvf, cudaFuncAttributeMaxDynamicSharedMemorySize, SMEM_TOT);
    cudaFuncSetAttribute(k_t_ut,     cudaFuncAttributeMaxDynamicSharedMemorySize, SMEM_TOT);

    h16 *xh,*wqth,*wkth,*wvth,*woh,*w1h,*wqkth,*m1th,*wvfh,*th,*uth,*ph;
    float *sc,*w2s;
    cudaGetSymbolAddress((void**)&xh, g_xh);
    cudaGetSymbolAddress((void**)&wqth, g_wqth);
    cudaGetSymbolAddress((void**)&wkth, g_wkth);
    cudaGetSymbolAddress((void**)&wvth, g_wvth);
    cudaGetSymbolAddress((void**)&woh, g_woh);
    cudaGetSymbolAddress((void**)&w1h, g_w1h);
    cudaGetSymbolAddress((void**)&wqkth, g_wqkth);
    cudaGetSymbolAddress((void**)&m1th, g_m1th);
    cudaGetSymbolAddress((void**)&wvfh, g_wvfh);
    cudaGetSymbolAddress((void**)&th, g_th);
    cudaGetSymbolAddress((void**)&uth, g_uth);
    cudaGetSymbolAddress((void**)&ph, g_ph);
    cudaGetSymbolAddress((void**)&sc, g_sc);
    cudaGetSymbolAddress((void**)&w2s, g_w2s);

    const size_t SH = (size_t)SEQ * HD;
    const size_t SS = (size_t)SEQ * SEQ;
    const float WS = 64.0f;           // weight pre-scale 2^6

    w2sum_k<<<HD/256, 256>>>(W2);

    // inputs -> fp16 hi-only (scaled)
    chalf_k<<<(int)((size_t)TOK*HD/1024), 256>>>((const float4*)x, (uint2*)xh, 1.0f);
    chalf2_k<<<dim3(HD*HD/1024, 1, 2), 256>>>((const float4*)Wo, (uint2*)woh,
                                              (const float4*)W1, (uint2*)w1h, WS);
    thalf3_k<<<dim3(HD/32, HD/32, 3), dim3(32, 8)>>>(Wq, wqth, Wk, wkth, Wv, wvth, WS);

    // M1t = NT(Wv^T, Wo); store s=6: os=2^(6-12)
    mma_one<0><<<dim3(16, 16, 1), NTHREADS, SMEM_TOT>>>(wvth, woh, m1th, nullptr,
                                                        nullptr, 0.015625f, 0,0,0);
    // merged: Wqkt = NT(Wk^T, Wq^T) os 2^-6 ; Wvf = NT(W1, M1t) os 2^-5
    k_wqkt_wvf<<<dim3(16, 16, 2), NTHREADS, SMEM_TOT>>>(wkth, wqth, wqkth,
                                                        w1h, m1th, wvfh);
    // merged: t = NT(x, Wqkt) s=1 ; uT[b] = NT(Wvf, x[b]) s=2 ; both os 2^-5
    k_t_ut<<<dim3(16, 128, 1), NTHREADS, SMEM_TOT>>>(xh, wqkth, th, wvfh, uth);

    // score[b] = NT(t[b], x[b]) fp32; os=2^(0-1-0)
    mma_one<1><<<dim3(16, 16, NB), NTHREADS, SMEM_TOT>>>(th, xh, nullptr, sc,
                                                         nullptr, 0.5f, SH, SH, SS);

    softmax_k<<<NB*SEQ, 256>>>(sc, ph);

    // Z[b] = NT(P[b], uT[b]) reduce; os=2^(0-0-2)
    mma_one<2><<<dim3(16, 16, NB), NTHREADS, SMEM_TOT>>>(ph, uth, nullptr, nullptr,
                                                         w2s, 0.25f, SS, SH, 0);

    out_k<<<1,1>>>((float*)d_out);
}

// round 14
// speedup vs baseline: 1.0257x; 1.0004x over previous
#include <cuda_runtime.h>
#include <cuda_fp16.h>
#include <cstdint>

#define HD   2048
#define SEQ  2048
#define NB   4
#define TOK  (NB*SEQ)
#define KDIM 2048
#define BM   128
#define BN   128
#define BK   64                 // fp16 elems = 128 bytes per row
#define KITERS (KDIM/BK)        // 32
#define NTHREADS 128

typedef __half h16;

// ---------------- static device scratch (fp16 hi-only, scaled domains) --------
__device__ h16  g_xh[(size_t)TOK*HD];                             // x    s=0
__device__ h16  g_wqth[(size_t)HD*HD];                            // Wq^T s=6
__device__ h16  g_wkth[(size_t)HD*HD];                            // Wk^T s=6
__device__ h16  g_wvth[(size_t)HD*HD];                            // Wv^T s=6
__device__ h16  g_woh[(size_t)HD*HD];                             // Wo   s=6
__device__ h16  g_w1h[(size_t)HD*HD];                             // W1   s=6
__device__ h16  g_wqkth[(size_t)HD*HD];                           // (Wq^T Wk)^T s=6
__device__ h16  g_m1th[(size_t)HD*HD];                            // (Wo Wv)^T   s=6
__device__ h16  g_wvfh[(size_t)HD*HD];                            // W1WoWv s=7
__device__ h16  g_th[(size_t)TOK*HD];                             // t s=1
__device__ h16  g_uth[(size_t)TOK*HD];                            // u^T s=2
__device__ h16  g_sch[(size_t)NB*SEQ*SEQ];                        // logits fp16
__device__ h16  g_ph[(size_t)NB*SEQ*SEQ];                         // P s=0
__device__ float g_w2s[HD];
__device__ double g_acc;

// ---------------- helpers -----------------------------------------------------
__device__ __forceinline__ uint32_t s2u(const void* p){
    uint32_t a;
    asm("{ .reg .u64 t; cvta.to.shared.u64 t, %1; cvt.u32.u64 %0, t; }" : "=r"(a) : "l"(p));
    return a;
}
__device__ __forceinline__ uint32_t pkh(h16 a, h16 b){
    __half2 t(a, b); return *reinterpret_cast<uint32_t*>(&t);
}

#define CPA(dst, src) asm volatile("cp.async.cg.shared.global [%0], [%1], 16;" \
    :: "r"(dst), "l"(src) : "memory")
#define CPA_COMMIT() asm volatile("cp.async.commit_group;" ::: "memory")

__device__ __forceinline__ void ldm4(uint32_t* r, uint32_t addr){
    asm volatile("ldmatrix.sync.aligned.m8n8.x4.shared.b16 {%0,%1,%2,%3}, [%4];"
        : "=r"(r[0]), "=r"(r[1]), "=r"(r[2]), "=r"(r[3]) : "r"(addr));
}
__device__ __forceinline__ void mma_f16(float* d, const uint32_t* a, const uint32_t* b){
    asm volatile(
        "mma.sync.aligned.m16n8k16.row.col.f32.f16.f16.f32 "
        "{%0,%1,%2,%3}, {%4,%5,%6,%7}, {%8,%9}, {%0,%1,%2,%3};"
        : "+f"(d[0]), "+f"(d[1]), "+f"(d[2]), "+f"(d[3])
        : "r"(a[0]), "r"(a[1]), "r"(a[2]), "r"(a[3]), "r"(b[0]), "r"(b[1]));
}

#define TILE_B   16384
#define STAGE_B  32768
#define NSTAGE   3
#define SMEM_TOT (NSTAGE*STAGE_B)    // 96KB -> 2 CTAs/SM

// ---------------- 1-term fp16 GEMM device body ---------------------------------
// C[m,n] = oscale * sum_k A[m,k]*B[n,k]  (NT), K=2048, leading dims 2048.
// 128 threads, 2x2 warps of 64x64 tiles. Caller pre-offsets pointers per batch.
// MODE 0: write fp16 Ch ; 2: sum(relu(C)*w2s) -> g_acc
template<int MODE>
__device__ __forceinline__ void gemm_body(
    const h16* __restrict__ Ah, const h16* __restrict__ Bh,
    h16* __restrict__ Ch,
    const float* __restrict__ w2s, float oscale,
    int bm, int bn, char* smem)
{
    const uint32_t sb = s2u(smem);

    const int tid = threadIdx.x;
    const int l   = tid & 31;
    const int wid = tid >> 5;         // 0..3
    const int wm  = wid & 1;          // 2 warps along M (64 rows each)
    const int wn  = wid >> 1;         // 2 warps along N (64 cols each)

    // ---- producer (cp.async) addressing: 128 threads cover 16 rows x 128B
    const int pr = tid >> 3;                 // 0..15 base row
    const int pc = (tid & 7) * 16;           // byte col in 128B row
    const uint32_t pdst = (uint32_t)pr * 128u + ((uint32_t)pc ^ (((uint32_t)pr & 7u) << 4));
    const char* gAh = (const char*)(Ah + (size_t)(bm + pr) * KDIM) + pc;
    const char* gBh = (const char*)(Bh + (size_t)(bn + pr) * KDIM) + pc;

    // ---- consumer (ldmatrix) addressing
    const int ar    = wm * 64 + (l & 15);
    const int akoff = (l >> 4) * 16;
    const uint32_t xA = ((uint32_t)ar & 7u) << 4;
    const int br    = wn * 64 + (l & 7) + ((l >> 4) & 1) * 8;   // + p*16
    const int bkoff = ((l >> 3) & 1) * 16;
    const uint32_t xB = ((uint32_t)br & 7u) << 4;

    float acc[4][8][4];
    #pragma unroll
    for (int i = 0; i < 4; i++)
        #pragma unroll
        for (int j = 0; j < 8; j++)
            #pragma unroll
            for (int r = 0; r < 4; r++) acc[i][j][r] = 0.f;

    // ---- prologue: chunks 0,1 into bufs 0,1 (8 row-strides of 16 rows each)
    #pragma unroll
    for (int s = 0; s < NSTAGE - 1; s++){
        const uint32_t s0 = sb + (uint32_t)s * STAGE_B;
        const size_t ko = (size_t)s * 128;
        #pragma unroll
        for (int j = 0; j < 8; j++){
            const size_t go = (size_t)j * 65536 + ko;     // +16 rows
            CPA(s0 +          pdst + j*2048, gAh + go);
            CPA(s0 + TILE_B + pdst + j*2048, gBh + go);
        }
        CPA_COMMIT();
    }

    int bufc = 0;
    int bufp = NSTAGE - 1;
    #pragma unroll 1
    for (int i = 0; i < KITERS; i++){
        asm volatile("cp.async.wait_group 1;" ::: "memory");
        __syncthreads();

        // produce chunk i+2 into the just-freed buffer (after sync => safe)
        if (i + NSTAGE - 1 < KITERS){
            const uint32_t s0 = sb + (uint32_t)bufp * STAGE_B;
            const size_t ko = (size_t)(i + NSTAGE - 1) * 128;
            #pragma unroll
            for (int j = 0; j < 8; j++){
                const size_t go = (size_t)j * 65536 + ko;
                CPA(s0 +          pdst + j*2048, gAh + go);
                CPA(s0 + TILE_B + pdst + j*2048, gBh + go);
            }
        }
        CPA_COMMIT();   // always commit to keep group counting aligned

        const uint32_t s0 = sb + (uint32_t)bufc * STAGE_B;
        #pragma unroll
        for (int ks = 0; ks < 4; ks++){
            const uint32_t kb = (uint32_t)ks * 32;
            uint32_t ah[4][4];
            #pragma unroll
            for (int fm = 0; fm < 4; fm++){
                uint32_t ad = s0 + (uint32_t)(ar + fm*16) * 128u + ((kb + akoff) ^ xA);
                ldm4(ah[fm], ad);
            }
            #pragma unroll
            for (int p = 0; p < 4; p++){          // stream B: 16 N-rows -> 2 fn
                uint32_t bh[4];
                uint32_t bd = s0 + TILE_B + (uint32_t)(br + p*16) * 128u + ((kb + bkoff) ^ xB);
                ldm4(bh, bd);
                #pragma unroll
                for (int fm = 0; fm < 4; fm++){
                    mma_f16(acc[fm][2*p + 0], ah[fm], &bh[0]);
                    mma_f16(acc[fm][2*p + 1], ah[fm], &bh[2]);
                }
            }
        }

        bufc = (bufc + 1 == NSTAGE) ? 0 : bufc + 1;
        bufp = (bufp + 1 == NSTAGE) ? 0 : bufp + 1;
    }

    // ---- epilogue
    const int crow = l >> 2;
    const int ccol = (l & 3) * 2;
    double local = 0.0;

    #pragma unroll
    for (int fm = 0; fm < 4; fm++){
        #pragma unroll
        for (int fn = 0; fn < 8; fn++){
            const int m0 = bm + wm*64 + fm*16 + crow;
            const int n0 = bn + wn*64 + fn*8 + ccol;
            const float* c = acc[fm][fn];
            if (MODE == 0){
                const size_t o0 = (size_t)m0 * KDIM + n0;
                const size_t o1 = (size_t)(m0+8) * KDIM + n0;
                *(uint32_t*)(Ch + o0) = pkh(__float2half_rn(c[0]*oscale),
                                            __float2half_rn(c[1]*oscale));
                *(uint32_t*)(Ch + o1) = pkh(__float2half_rn(c[2]*oscale),
                                            __float2half_rn(c[3]*oscale));
            } else {
                float w0 = w2s[n0], w1 = w2s[n0+1];
                float z;
                z = c[0]*oscale; local += (double)((z > 0.f ? z : 0.f) * w0);
                z = c[1]*oscale; local += (double)((z > 0.f ? z : 0.f) * w1);
                z = c[2]*oscale; local += (double)((z > 0.f ? z : 0.f) * w0);
                z = c[3]*oscale; local += (double)((z > 0.f ? z : 0.f) * w1);
            }
        }
    }

    if (MODE == 2){
        __syncthreads();
        double* red = (double*)smem;
        red[tid] = local;
        __syncthreads();
        #pragma unroll
        for (int s = 64; s > 0; s >>= 1){
            if (tid < s) red[tid] += red[tid + s];
            __syncthreads();
        }
        if (tid == 0) atomicAdd(&g_acc, red[0]);
    }
}

// ---------------- GEMM kernels --------------------------------------------------
// batched (z) GEMM with per-batch strides
template<int MODE>
__global__ void __launch_bounds__(NTHREADS, 2) mma_one(
    const h16* __restrict__ Ah, const h16* __restrict__ Bh,
    h16* __restrict__ Ch, const float* __restrict__ w2s, float oscale,
    size_t sA, size_t sB, size_t sC)
{
    extern __shared__ char smem[];
    const size_t zo = blockIdx.z;
    gemm_body<MODE>(Ah + zo*sA, Bh + zo*sB,
                    (MODE == 0) ? Ch + zo*sC : nullptr,
                    w2s, oscale, blockIdx.y * BM, blockIdx.x * BN, smem);
}

// merged: z=0 -> Wqkt = NT(Wk^T, Wq^T) os 2^-6 ; z=1 -> Wvf = NT(W1, M1t) os 2^-5
__global__ void __launch_bounds__(NTHREADS, 2) k_wqkt_wvf(
    const h16* __restrict__ wkth, const h16* __restrict__ wqth, h16* __restrict__ wqkth,
    const h16* __restrict__ w1h,  const h16* __restrict__ m1th, h16* __restrict__ wvfh)
{
    extern __shared__ char smem[];
    const h16 *A, *B; h16* C; float os;
    if (blockIdx.z == 0){ A = wkth; B = wqth; C = wqkth; os = 0.015625f; }
    else                { A = w1h;  B = m1th; C = wvfh;  os = 0.03125f;  }
    gemm_body<0>(A, B, C, nullptr, os, blockIdx.y * BM, blockIdx.x * BN, smem);
}

// merged: y<64 -> t = NT(x, Wqkt) ; y>=64 -> uT[b] = NT(Wvf, x[b]) ; both os 2^-5
__global__ void __launch_bounds__(NTHREADS, 2) k_t_ut(
    const h16* __restrict__ xh, const h16* __restrict__ wqkth, h16* __restrict__ th,
    const h16* __restrict__ wvfh, h16* __restrict__ uth)
{
    extern __shared__ char smem[];
    const size_t SH = (size_t)SEQ * HD;
    const int y = blockIdx.y;
    const h16 *A, *B; h16* C; int bm;
    if (y < 64){            // t
        A = xh;  B = wqkth;  C = th;  bm = y * BM;
    } else {                // uT, batch b
        const int yy = y - 64;
        const int b  = yy >> 4;
        A = wvfh;  B = xh + (size_t)b * SH;  C = uth + (size_t)b * SH;
        bm = (yy & 15) * BM;
    }
    gemm_body<0>(A, B, C, nullptr, 0.03125f, bm, blockIdx.x * BN, smem);
}

// ---------------- aux kernels -------------------------------------------------
__global__ void chalf_k(const float4* __restrict__ in, uint2* __restrict__ oh,
                        float scale)
{
    size_t i = (size_t)blockIdx.x * 256 + threadIdx.x;
    float4 f = in[i];
    oh[i] = make_uint2(pkh(__float2half_rn(f.x*scale), __float2half_rn(f.y*scale)),
                       pkh(__float2half_rn(f.z*scale), __float2half_rn(f.w*scale)));
}

// merged weight chalf: z selects (Wo, W1)
__global__ void chalf2_k(const float4* __restrict__ w0, uint2* __restrict__ o0,
                         const float4* __restrict__ w1, uint2* __restrict__ o1,
                         float scale)
{
    size_t i = (size_t)blockIdx.x * 256 + threadIdx.x;
    const float4* in = (blockIdx.z == 0) ? w0 : w1;
    uint2* oh        = (blockIdx.z == 0) ? o0 : o1;
    float4 f = in[i];
    oh[i] = make_uint2(pkh(__float2half_rn(f.x*scale), __float2half_rn(f.y*scale)),
                       pkh(__float2half_rn(f.z*scale), __float2half_rn(f.w*scale)));
}

// merged transpose: out[C][R] = in[R][C] * scale ; z selects (Wq, Wk, Wv)
__global__ void thalf3_k(const float* __restrict__ i0, h16* __restrict__ o0,
                         const float* __restrict__ i1, h16* __restrict__ o1,
                         const float* __restrict__ i2, h16* __restrict__ o2,
                         float scale)
{
    __shared__ float t[32][33];
    const float* in = (blockIdx.z == 0) ? i0 : (blockIdx.z == 1) ? i1 : i2;
    h16* oh         = (blockIdx.z == 0) ? o0 : (blockIdx.z == 1) ? o1 : o2;
    int c0 = blockIdx.x * 32, r0 = blockIdx.y * 32;
    int tx = threadIdx.x, ty = threadIdx.y;
    #pragma unroll
    for (int j = 0; j < 32; j += 8)
        t[ty + j][tx] = in[(size_t)(r0 + ty + j) * HD + c0 + tx];
    __syncthreads();
    #pragma unroll
    for (int j = 0; j < 32; j += 8){
        size_t o = (size_t)(c0 + ty + j) * HD + r0 + tx;
        oh[o] = __float2half_rn(t[tx][ty + j] * scale);
    }
}

// row softmax over fp16 logits -> fp16 probs; 256 threads, 8 halves/thread
__global__ void softmax_k(const h16* __restrict__ S, h16* __restrict__ Ph)
{
    const size_t ro = (size_t)blockIdx.x * SEQ;
    const uint4* rin = (const uint4*)(S + ro);
    uint4* rout      = (uint4*)(Ph + ro);
    const int tid = threadIdx.x;  // 256
    __shared__ float sm[256];

    uint4 raw = rin[tid];
    const __half2* hp = (const __half2*)&raw;
    float v[8];
    #pragma unroll
    for (int t = 0; t < 4; t++){
        float2 f = __half22float2(hp[t]);
        v[2*t] = f.x;  v[2*t+1] = f.y;
    }

    float mx = -3.0e38f;
    #pragma unroll
    for (int t = 0; t < 8; t++) mx = fmaxf(mx, v[t]);
    sm[tid] = mx; __syncthreads();
    #pragma unroll
    for (int s = 128; s > 0; s >>= 1){
        if (tid < s) sm[tid] = fmaxf(sm[tid], sm[tid + s]);
        __syncthreads();
    }
    mx = sm[0]; __syncthreads();

    float sum = 0.f;
    #pragma unroll
    for (int t = 0; t < 8; t++){ v[t] = expf(v[t] - mx); sum += v[t]; }
    sm[tid] = sum; __syncthreads();
    #pragma unroll
    for (int s = 128; s > 0; s >>= 1){
        if (tid < s) sm[tid] += sm[tid + s];
        __syncthreads();
    }
    float inv = 1.0f / sm[0];

    uint4 out;
    __half2* op = (__half2*)&out;
    #pragma unroll
    for (int t = 0; t < 4; t++)
        op[t] = __floats2half2_rn(v[2*t] * inv, v[2*t+1] * inv);
    rout[tid] = out;
}

__global__ void w2sum_k(const float* __restrict__ W2)
{
    int e = blockIdx.x * 256 + threadIdx.x;
    if (e == 0) g_acc = 0.0;
    float s = 0.f;
    for (int d = 0; d < HD; d++) s += W2[(size_t)d * HD + e];
    g_w2s[e] = s;
}

__global__ void out_k(float* __restrict__ out){ out[0] = (float)g_acc; }

// ---------------- launch --------------------------------------------------------
extern "C" void kernel_launch(void* const* d_in, const int* in_sizes, int n_in,
                              void* d_out, int out_size)
{
    const float* x  = (const float*)d_in[0];
    const float* Wq = (const float*)d_in[1];
    const float* Wk = (const float*)d_in[2];
    const float* Wv = (const float*)d_in[3];
    const float* Wo = (const float*)d_in[4];
    const float* W1 = (const float*)d_in[5];
    const float* W2 = (const float*)d_in[6];

    cudaFuncSetAttribute(mma_one<0>, cudaFuncAttributeMaxDynamicSharedMemorySize, SMEM_TOT);
    cudaFuncSetAttribute(mma_one<2>, cudaFuncAttributeMaxDynamicSharedMemorySize, SMEM_TOT);
    cudaFuncSetAttribute(k_wqkt_wvf, cudaFuncAttributeMaxDynamicSharedMemorySize, SMEM_TOT);
    cudaFuncSetAttribute(k_t_ut,     cudaFuncAttributeMaxDynamicSharedMemorySize, SMEM_TOT);

    h16 *xh,*wqth,*wkth,*wvth,*woh,*w1h,*wqkth,*m1th,*wvfh,*th,*uth,*sch,*ph;
    float *w2s;
    cudaGetSymbolAddress((void**)&xh, g_xh);
    cudaGetSymbolAddress((void**)&wqth, g_wqth);
    cudaGetSymbolAddress((void**)&wkth, g_wkth);
    cudaGetSymbolAddress((void**)&wvth, g_wvth);
    cudaGetSymbolAddress((void**)&woh, g_woh);
    cudaGetSymbolAddress((void**)&w1h, g_w1h);
    cudaGetSymbolAddress((void**)&wqkth, g_wqkth);
    cudaGetSymbolAddress((void**)&m1th, g_m1th);
    cudaGetSymbolAddress((void**)&wvfh, g_wvfh);
    cudaGetSymbolAddress((void**)&th, g_th);
    cudaGetSymbolAddress((void**)&uth, g_uth);
    cudaGetSymbolAddress((void**)&sch, g_sch);
    cudaGetSymbolAddress((void**)&ph, g_ph);
    cudaGetSymbolAddress((void**)&w2s, g_w2s);

    const size_t SH = (size_t)SEQ * HD;
    const size_t SS = (size_t)SEQ * SEQ;
    const float WS = 64.0f;           // weight pre-scale 2^6

    w2sum_k<<<HD/256, 256>>>(W2);

    // inputs -> fp16 hi-only (scaled)
    chalf_k<<<(int)((size_t)TOK*HD/1024), 256>>>((const float4*)x, (uint2*)xh, 1.0f);
    chalf2_k<<<dim3(HD*HD/1024, 1, 2), 256>>>((const float4*)Wo, (uint2*)woh,
                                              (const float4*)W1, (uint2*)w1h, WS);
    thalf3_k<<<dim3(HD/32, HD/32, 3), dim3(32, 8)>>>(Wq, wqth, Wk, wkth, Wv, wvth, WS);

    // M1t = NT(Wv^T, Wo); store s=6: os=2^(6-12)
    mma_one<0><<<dim3(16, 16, 1), NTHREADS, SMEM_TOT>>>(wvth, woh, m1th, nullptr,
                                                        0.015625f, 0,0,0);
    // merged: Wqkt = NT(Wk^T, Wq^T) os 2^-6 ; Wvf = NT(W1, M1t) os 2^-5
    k_wqkt_wvf<<<dim3(16, 16, 2), NTHREADS, SMEM_TOT>>>(wkth, wqth, wqkth, w1h, m1th, wvfh);
    // merged: t = NT(x, Wqkt) s=1 ; uT[b] = NT(Wvf, x[b]) s=2 ; both os 2^-5
    k_t_ut<<<dim3(16, 128, 1), NTHREADS, SMEM_TOT>>>(xh, wqkth, th, wvfh, uth);

    // score[b] = NT(t[b], x[b]) -> fp16 logits; os=2^(0-1-0)
    mma_one<0><<<dim3(16, 16, NB), NTHREADS, SMEM_TOT>>>(th, xh, sch, nullptr,
                                                         0.5f, SH, SH, SS);

    softmax_k<<<NB*SEQ, 256>>>(sch, ph);

    // Z[b] = NT(P[b], uT[b]) reduce; os=2^(0-0-2)
    mma_one<2><<<dim3(16, 16, NB), NTHREADS, SMEM_TOT>>>(ph, uth, nullptr, w2s,
                                                         0.25f, SS, SH, 0);

    out_k<<<1,1>>>((float*)d_out);
}

// round 16
// speedup vs baseline: 1.0299x; 1.0042x over previous
#include <cuda_runtime.h>
#include <cuda_fp16.h>
#include <cstdint>

#define HD   2048
#define SEQ  2048
#define NB   4
#define TOK  (NB*SEQ)
#define KDIM 2048
#define BM   128
#define BN   128
#define BK   64                 // fp16 elems = 128 bytes per row
#define KITERS (KDIM/BK)        // 32
#define NTHREADS 128

typedef __half h16;

// ---------------- static device scratch (fp16 hi-only, scaled domains) --------
__device__ h16  g_xh[(size_t)TOK*HD];                             // x    s=0
__device__ h16  g_wqth[(size_t)HD*HD];                            // Wq^T s=6
__device__ h16  g_wkth[(size_t)HD*HD];                            // Wk^T s=6
__device__ h16  g_wvth[(size_t)HD*HD];                            // Wv^T s=6
__device__ h16  g_woh[(size_t)HD*HD];                             // Wo   s=6
__device__ h16  g_w1h[(size_t)HD*HD];                             // W1   s=6
__device__ h16  g_wqkth[(size_t)HD*HD];                           // (Wq^T Wk)^T s=6
__device__ h16  g_m1th[(size_t)HD*HD];                            // (Wo Wv)^T   s=6
__device__ h16  g_wvfh[(size_t)HD*HD];                            // W1WoWv s=7
__device__ h16  g_th[(size_t)TOK*HD];                             // t s=1
__device__ h16  g_uth[(size_t)TOK*HD];                            // u^T s=2
__device__ h16  g_sch[(size_t)NB*SEQ*SEQ];                        // logits fp16
__device__ h16  g_ph[(size_t)NB*SEQ*SEQ];                         // P s=0
__device__ float g_w2s[HD];
__device__ double g_acc;

// ---------------- helpers -----------------------------------------------------
__device__ __forceinline__ uint32_t s2u(const void* p){
    uint32_t a;
    asm("{ .reg .u64 t; cvta.to.shared.u64 t, %1; cvt.u32.u64 %0, t; }" : "=r"(a) : "l"(p));
    return a;
}
__device__ __forceinline__ uint32_t pkh(h16 a, h16 b){
    __half2 t(a, b); return *reinterpret_cast<uint32_t*>(&t);
}

#define CPA(dst, src) asm volatile("cp.async.cg.shared.global [%0], [%1], 16;" \
    :: "r"(dst), "l"(src) : "memory")
#define CPA_COMMIT() asm volatile("cp.async.commit_group;" ::: "memory")

__device__ __forceinline__ void ldm4(uint32_t* r, uint32_t addr){
    asm volatile("ldmatrix.sync.aligned.m8n8.x4.shared.b16 {%0,%1,%2,%3}, [%4];"
        : "=r"(r[0]), "=r"(r[1]), "=r"(r[2]), "=r"(r[3]) : "r"(addr));
}
__device__ __forceinline__ void mma_f16(float* d, const uint32_t* a, const uint32_t* b){
    asm volatile(
        "mma.sync.aligned.m16n8k16.row.col.f32.f16.f16.f32 "
        "{%0,%1,%2,%3}, {%4,%5,%6,%7}, {%8,%9}, {%0,%1,%2,%3};"
        : "+f"(d[0]), "+f"(d[1]), "+f"(d[2]), "+f"(d[3])
        : "r"(a[0]), "r"(a[1]), "r"(a[2]), "r"(a[3]), "r"(b[0]), "r"(b[1]));
}

#define TILE_B   16384
#define STAGE_B  32768
#define NSTAGE   3
#define SMEM_TOT (NSTAGE*STAGE_B)    // 96KB -> 2 CTAs/SM

// ---------------- 1-term fp16 GEMM device body ---------------------------------
// C[m,n] = oscale * sum_k A[m,k]*B[n,k]  (NT), K=2048, leading dims 2048.
// 128 threads, 2x2 warps of 64x64 tiles. Caller pre-offsets pointers per batch.
// MODE 0: write fp16 Ch ; 2: sum(relu(C)*w2s) -> g_acc
// Mainloop order (R14-proven): wait_group -> __syncthreads -> produce -> consume.
// The barrier AFTER the wait is what makes other threads' cp.async completions
// visible to this thread's ldmatrix — do not reorder (R15 bug).
template<int MODE>
__device__ __forceinline__ void gemm_body(
    const h16* __restrict__ Ah, const h16* __restrict__ Bh,
    h16* __restrict__ Ch,
    const float* __restrict__ w2s, float oscale,
    int bm, int bn, char* smem)
{
    const uint32_t sb = s2u(smem);

    const int tid = threadIdx.x;
    const int l   = tid & 31;
    const int wid = tid >> 5;         // 0..3
    const int wm  = wid & 1;          // 2 warps along M (64 rows each)
    const int wn  = wid >> 1;         // 2 warps along N (64 cols each)

    // ---- producer (cp.async) addressing: 128 threads cover 16 rows x 128B
    const int pr = tid >> 3;                 // 0..15 base row
    const int pc = (tid & 7) * 16;           // byte col in 128B row
    const uint32_t pdst = (uint32_t)pr * 128u + ((uint32_t)pc ^ (((uint32_t)pr & 7u) << 4));
    const char* gAh = (const char*)(Ah + (size_t)(bm + pr) * KDIM) + pc;
    const char* gBh = (const char*)(Bh + (size_t)(bn + pr) * KDIM) + pc;

    // ---- consumer (ldmatrix) addressing
    const int ar    = wm * 64 + (l & 15);
    const int akoff = (l >> 4) * 16;
    const uint32_t xA = ((uint32_t)ar & 7u) << 4;
    const int br    = wn * 64 + (l & 7) + ((l >> 4) & 1) * 8;   // + p*16
    const int bkoff = ((l >> 3) & 1) * 16;
    const uint32_t xB = ((uint32_t)br & 7u) << 4;

    float acc[4][8][4];
    #pragma unroll
    for (int i = 0; i < 4; i++)
        #pragma unroll
        for (int j = 0; j < 8; j++)
            #pragma unroll
            for (int r = 0; r < 4; r++) acc[i][j][r] = 0.f;

    // ---- prologue: chunks 0,1 into bufs 0,1 (8 row-strides of 16 rows each)
    #pragma unroll
    for (int s = 0; s < NSTAGE - 1; s++){
        const uint32_t s0 = sb + (uint32_t)s * STAGE_B;
        const size_t ko = (size_t)s * 128;
        #pragma unroll
        for (int j = 0; j < 8; j++){
            const size_t go = (size_t)j * 65536 + ko;     // +16 rows
            CPA(s0 +          pdst + j*2048, gAh + go);
            CPA(s0 + TILE_B + pdst + j*2048, gBh + go);
        }
        CPA_COMMIT();
    }

    int bufc = 0;
    int bufp = NSTAGE - 1;
    #pragma unroll 1
    for (int i = 0; i < KITERS; i++){
        asm volatile("cp.async.wait_group 1;" ::: "memory");
        __syncthreads();

        // produce chunk i+2 into the just-freed buffer (after sync => safe)
        if (i + NSTAGE - 1 < KITERS){
            const uint32_t s0 = sb + (uint32_t)bufp * STAGE_B;
            const size_t ko = (size_t)(i + NSTAGE - 1) * 128;
            #pragma unroll
            for (int j = 0; j < 8; j++){
                const size_t go = (size_t)j * 65536 + ko;
                CPA(s0 +          pdst + j*2048, gAh + go);
                CPA(s0 + TILE_B + pdst + j*2048, gBh + go);
            }
        }
        CPA_COMMIT();   // always commit to keep group counting aligned

        const uint32_t s0 = sb + (uint32_t)bufc * STAGE_B;
        #pragma unroll
        for (int ks = 0; ks < 4; ks++){
            const uint32_t kb = (uint32_t)ks * 32;
            uint32_t ah[4][4];
            #pragma unroll
            for (int fm = 0; fm < 4; fm++){
                uint32_t ad = s0 + (uint32_t)(ar + fm*16) * 128u + ((kb + akoff) ^ xA);
                ldm4(ah[fm], ad);
            }
            #pragma unroll
            for (int p = 0; p < 4; p++){          // stream B: 16 N-rows -> 2 fn
                uint32_t bh[4];
                uint32_t bd = s0 + TILE_B + (uint32_t)(br + p*16) * 128u + ((kb + bkoff) ^ xB);
                ldm4(bh, bd);
                #pragma unroll
                for (int fm = 0; fm < 4; fm++){
                    mma_f16(acc[fm][2*p + 0], ah[fm], &bh[0]);
                    mma_f16(acc[fm][2*p + 1], ah[fm], &bh[2]);
                }
            }
        }

        bufc = (bufc + 1 == NSTAGE) ? 0 : bufc + 1;
        bufp = (bufp + 1 == NSTAGE) ? 0 : bufp + 1;
    }

    // ---- epilogue
    const int crow = l >> 2;
    const int ccol = (l & 3) * 2;
    double local = 0.0;

    #pragma unroll
    for (int fm = 0; fm < 4; fm++){
        #pragma unroll
        for (int fn = 0; fn < 8; fn++){
            const int m0 = bm + wm*64 + fm*16 + crow;
            const int n0 = bn + wn*64 + fn*8 + ccol;
            const float* c = acc[fm][fn];
            if (MODE == 0){
                const size_t o0 = (size_t)m0 * KDIM + n0;
                const size_t o1 = (size_t)(m0+8) * KDIM + n0;
                *(uint32_t*)(Ch + o0) = pkh(__float2half_rn(c[0]*oscale),
                                            __float2half_rn(c[1]*oscale));
                *(uint32_t*)(Ch + o1) = pkh(__float2half_rn(c[2]*oscale),
                                            __float2half_rn(c[3]*oscale));
            } else {
                float w0 = w2s[n0], w1 = w2s[n0+1];
                float z;
                z = c[0]*oscale; local += (double)((z > 0.f ? z : 0.f) * w0);
                z = c[1]*oscale; local += (double)((z > 0.f ? z : 0.f) * w1);
                z = c[2]*oscale; local += (double)((z > 0.f ? z : 0.f) * w0);
                z = c[3]*oscale; local += (double)((z > 0.f ? z : 0.f) * w1);
            }
        }
    }

    if (MODE == 2){
        __syncthreads();
        double* red = (double*)smem;
        red[tid] = local;
        __syncthreads();
        #pragma unroll
        for (int s = 64; s > 0; s >>= 1){
            if (tid < s) red[tid] += red[tid + s];
            __syncthreads();
        }
        if (tid == 0) atomicAdd(&g_acc, red[0]);
    }
}

// ---------------- GEMM kernels --------------------------------------------------
// batched (z) GEMM with per-batch strides
template<int MODE>
__global__ void __launch_bounds__(NTHREADS, 2) mma_one(
    const h16* __restrict__ Ah, const h16* __restrict__ Bh,
    h16* __restrict__ Ch, const float* __restrict__ w2s, float oscale,
    size_t sA, size_t sB, size_t sC)
{
    extern __shared__ char smem[];
    const size_t zo = blockIdx.z;
    gemm_body<MODE>(Ah + zo*sA, Bh + zo*sB,
                    (MODE == 0) ? Ch + zo*sC : nullptr,
                    w2s, oscale, blockIdx.y * BM, blockIdx.x * BN, smem);
}

// launch1: z=0 -> Wqkt = NT(Wk^T, Wq^T) ; z=1 -> M1t = NT(Wv^T, Wo) ; both os 2^-6
__global__ void __launch_bounds__(NTHREADS, 2) k_wqkt_m1t(
    const h16* __restrict__ wkth, const h16* __restrict__ wqth, h16* __restrict__ wqkth,
    const h16* __restrict__ wvth, const h16* __restrict__ woh,  h16* __restrict__ m1th)
{
    extern __shared__ char smem[];
    const h16 *A, *B; h16* C;
    if (blockIdx.z == 0){ A = wkth; B = wqth; C = wqkth; }
    else                { A = wvth; B = woh;  C = m1th;  }
    gemm_body<0>(A, B, C, nullptr, 0.015625f, blockIdx.y * BM, blockIdx.x * BN, smem);
}

// launch2: y<16 -> Wvf = NT(W1, M1t) ; y>=16 -> t = NT(x, Wqkt) ; both os 2^-5
__global__ void __launch_bounds__(NTHREADS, 2) k_wvf_t(
    const h16* __restrict__ w1h, const h16* __restrict__ m1th, h16* __restrict__ wvfh,
    const h16* __restrict__ xh,  const h16* __restrict__ wqkth, h16* __restrict__ th)
{
    extern __shared__ char smem[];
    const int y = blockIdx.y;
    const h16 *A, *B; h16* C; int bm;
    if (y < 16){ A = w1h; B = m1th;  C = wvfh; bm = y * BM; }
    else       { A = xh;  B = wqkth; C = th;   bm = (y - 16) * BM; }
    gemm_body<0>(A, B, C, nullptr, 0.03125f, bm, blockIdx.x * BN, smem);
}

// launch3: y<64 -> score[b] = NT(t[b], x[b]) os 0.5 ; y>=64 -> uT[b] = NT(Wvf, x[b]) os 2^-5
__global__ void __launch_bounds__(NTHREADS, 2) k_score_ut(
    const h16* __restrict__ th, const h16* __restrict__ xh, h16* __restrict__ sch,
    const h16* __restrict__ wvfh, h16* __restrict__ uth)
{
    extern __shared__ char smem[];
    const size_t SH = (size_t)SEQ * HD;
    const size_t SS = (size_t)SEQ * SEQ;
    const int y = blockIdx.y;
    const h16 *A, *B; h16* C; int bm; float os;
    if (y < 64){            // score, batch b
        const int b = y >> 4;
        A = th + (size_t)b * SH;  B = xh + (size_t)b * SH;  C = sch + (size_t)b * SS;
        bm = (y & 15) * BM;  os = 0.5f;
    } else {                // uT, batch b
        const int yy = y - 64;
        const int b  = yy >> 4;
        A = wvfh;  B = xh + (size_t)b * SH;  C = uth + (size_t)b * SH;
        bm = (yy & 15) * BM;  os = 0.03125f;
    }
    gemm_body<0>(A, B, C, nullptr, os, bm, blockIdx.x * BN, smem);
}

// ---------------- aux kernels -------------------------------------------------
__global__ void chalf_k(const float4* __restrict__ in, uint2* __restrict__ oh,
                        float scale)
{
    size_t i = (size_t)blockIdx.x * 256 + threadIdx.x;
    float4 f = in[i];
    oh[i] = make_uint2(pkh(__float2half_rn(f.x*scale), __float2half_rn(f.y*scale)),
                       pkh(__float2half_rn(f.z*scale), __float2half_rn(f.w*scale)));
}

// merged weight chalf: z selects (Wo, W1)
__global__ void chalf2_k(const float4* __restrict__ w0, uint2* __restrict__ o0,
                         const float4* __restrict__ w1, uint2* __restrict__ o1,
                         float scale)
{
    size_t i = (size_t)blockIdx.x * 256 + threadIdx.x;
    const float4* in = (blockIdx.z == 0) ? w0 : w1;
    uint2* oh        = (blockIdx.z == 0) ? o0 : o1;
    float4 f = in[i];
    oh[i] = make_uint2(pkh(__float2half_rn(f.x*scale), __float2half_rn(f.y*scale)),
                       pkh(__float2half_rn(f.z*scale), __float2half_rn(f.w*scale)));
}

// merged transpose: out[C][R] = in[R][C] * scale ; z selects (Wq, Wk, Wv)
__global__ void thalf3_k(const float* __restrict__ i0, h16* __restrict__ o0,
                         const float* __restrict__ i1, h16* __restrict__ o1,
                         const float* __restrict__ i2, h16* __restrict__ o2,
                         float scale)
{
    __shared__ float t[32][33];
    const float* in = (blockIdx.z == 0) ? i0 : (blockIdx.z == 1) ? i1 : i2;
    h16* oh         = (blockIdx.z == 0) ? o0 : (blockIdx.z == 1) ? o1 : o2;
    int c0 = blockIdx.x * 32, r0 = blockIdx.y * 32;
    int tx = threadIdx.x, ty = threadIdx.y;
    #pragma unroll
    for (int j = 0; j < 32; j += 8)
        t[ty + j][tx] = in[(size_t)(r0 + ty + j) * HD + c0 + tx];
    __syncthreads();
    #pragma unroll
    for (int j = 0; j < 32; j += 8){
        size_t o = (size_t)(c0 + ty + j) * HD + r0 + tx;
        oh[o] = __float2half_rn(t[tx][ty + j] * scale);
    }
}

// row softmax over fp16 logits -> fp16 probs; 256 threads, 8 halves/thread
__global__ void softmax_k(const h16* __restrict__ S, h16* __restrict__ Ph)
{
    const size_t ro = (size_t)blockIdx.x * SEQ;
    const uint4* rin = (const uint4*)(S + ro);
    uint4* rout      = (uint4*)(Ph + ro);
    const int tid = threadIdx.x;  // 256
    __shared__ float sm[256];

    uint4 raw = rin[tid];
    const __half2* hp = (const __half2*)&raw;
    float v[8];
    #pragma unroll
    for (int t = 0; t < 4; t++){
        float2 f = __half22float2(hp[t]);
        v[2*t] = f.x;  v[2*t+1] = f.y;
    }

    float mx = -3.0e38f;
    #pragma unroll
    for (int t = 0; t < 8; t++) mx = fmaxf(mx, v[t]);
    sm[tid] = mx; __syncthreads();
    #pragma unroll
    for (int s = 128; s > 0; s >>= 1){
        if (tid < s) sm[tid] = fmaxf(sm[tid], sm[tid + s]);
        __syncthreads();
    }
    mx = sm[0]; __syncthreads();

    float sum = 0.f;
    #pragma unroll
    for (int t = 0; t < 8; t++){ v[t] = expf(v[t] - mx); sum += v[t]; }
    sm[tid] = sum; __syncthreads();
    #pragma unroll
    for (int s = 128; s > 0; s >>= 1){
        if (tid < s) sm[tid] += sm[tid + s];
        __syncthreads();
    }
    float inv = 1.0f / sm[0];

    uint4 out;
    __half2* op = (__half2*)&out;
    #pragma unroll
    for (int t = 0; t < 4; t++)
        op[t] = __floats2half2_rn(v[2*t] * inv, v[2*t+1] * inv);
    rout[tid] = out;
}

__global__ void w2sum_k(const float* __restrict__ W2)
{
    int e = blockIdx.x * 256 + threadIdx.x;
    if (e == 0) g_acc = 0.0;
    float s = 0.f;
    for (int d = 0; d < HD; d++) s += W2[(size_t)d * HD + e];
    g_w2s[e] = s;
}

__global__ void out_k(float* __restrict__ out){ out[0] = (float)g_acc; }

// ---------------- launch --------------------------------------------------------
extern "C" void kernel_launch(void* const* d_in, const int* in_sizes, int n_in,
                              void* d_out, int out_size)
{
    const float* x  = (const float*)d_in[0];
    const float* Wq = (const float*)d_in[1];
    const float* Wk = (const float*)d_in[2];
    const float* Wv = (const float*)d_in[3];
    const float* Wo = (const float*)d_in[4];
    const float* W1 = (const float*)d_in[5];
    const float* W2 = (const float*)d_in[6];

    cudaFuncSetAttribute(mma_one<2>,  cudaFuncAttributeMaxDynamicSharedMemorySize, SMEM_TOT);
    cudaFuncSetAttribute(k_wqkt_m1t,  cudaFuncAttributeMaxDynamicSharedMemorySize, SMEM_TOT);
    cudaFuncSetAttribute(k_wvf_t,     cudaFuncAttributeMaxDynamicSharedMemorySize, SMEM_TOT);
    cudaFuncSetAttribute(k_score_ut,  cudaFuncAttributeMaxDynamicSharedMemorySize, SMEM_TOT);

    h16 *xh,*wqth,*wkth,*wvth,*woh,*w1h,*wqkth,*m1th,*wvfh,*th,*uth,*sch,*ph;
    float *w2s;
    cudaGetSymbolAddress((void**)&xh, g_xh);
    cudaGetSymbolAddress((void**)&wqth, g_wqth);
    cudaGetSymbolAddress((void**)&wkth, g_wkth);
    cudaGetSymbolAddress((void**)&wvth, g_wvth);
    cudaGetSymbolAddress((void**)&woh, g_woh);
    cudaGetSymbolAddress((void**)&w1h, g_w1h);
    cudaGetSymbolAddress((void**)&wqkth, g_wqkth);
    cudaGetSymbolAddress((void**)&m1th, g_m1th);
    cudaGetSymbolAddress((void**)&wvfh, g_wvfh);
    cudaGetSymbolAddress((void**)&th, g_th);
    cudaGetSymbolAddress((void**)&uth, g_uth);
    cudaGetSymbolAddress((void**)&sch, g_sch);
    cudaGetSymbolAddress((void**)&ph, g_ph);
    cudaGetSymbolAddress((void**)&w2s, g_w2s);

    const size_t SH = (size_t)SEQ * HD;
    const size_t SS = (size_t)SEQ * SEQ;
    const float WS = 64.0f;           // weight pre-scale 2^6

    w2sum_k<<<HD/256, 256>>>(W2);

    // inputs -> fp16 hi-only (scaled)
    chalf_k<<<(int)((size_t)TOK*HD/1024), 256>>>((const float4*)x, (uint2*)xh, 1.0f);
    chalf2_k<<<dim3(HD*HD/1024, 1, 2), 256>>>((const float4*)Wo, (uint2*)woh,
                                              (const float4*)W1, (uint2*)w1h, WS);
    thalf3_k<<<dim3(HD/32, HD/32, 3), dim3(32, 8)>>>(Wq, wqth, Wk, wkth, Wv, wvth, WS);

    // L1: Wqkt = NT(Wk^T, Wq^T) ; M1t = NT(Wv^T, Wo)   (both s=6, os=2^-6)
    k_wqkt_m1t<<<dim3(16, 16, 2), NTHREADS, SMEM_TOT>>>(wkth, wqth, wqkth,
                                                        wvth, woh, m1th);
    // L2: Wvf = NT(W1, M1t) s=7 ; t = NT(x, Wqkt) s=1   (both os=2^-5)
    k_wvf_t<<<dim3(16, 80, 1), NTHREADS, SMEM_TOT>>>(w1h, m1th, wvfh, xh, wqkth, th);
    // L3: score[b] = NT(t[b], x[b]) fp16 os=0.5 ; uT[b] = NT(Wvf, x[b]) s=2 os=2^-5
    k_score_ut<<<dim3(16, 128, 1), NTHREADS, SMEM_TOT>>>(th, xh, sch, wvfh, uth);

    softmax_k<<<NB*SEQ, 256>>>(sch, ph);

    // Z[b] = NT(P[b], uT[b]) reduce; os=2^(0-0-2)
    mma_one<2><<<dim3(16, 16, NB), NTHREADS, SMEM_TOT>>>(ph, uth, nullptr, w2s,
                                                         0.25f, SS, SH, 0);

    out_k<<<1,1>>>((float*)d_out);
}

// round 17
// speedup vs baseline: 1.0839x; 1.0524x over previous
#include <cuda_runtime.h>
#include <cuda_fp16.h>
#include <cstdint>

#define HD   2048
#define SEQ  2048
#define NB   4
#define TOK  (NB*SEQ)
#define KDIM 2048
#define BM   128
#define BN   128
#define BK   64                 // fp16 elems = 128 bytes per row
#define KITERS (KDIM/BK)        // 32
#define NTHREADS 128

typedef __half h16;

// ---------------- static device scratch (fp16 hi-only, scaled domains) --------
__device__ h16  g_xh[(size_t)TOK*HD];                             // x    s=0
__device__ h16  g_wqth[(size_t)HD*HD];                            // Wq^T s=6
__device__ h16  g_wkth[(size_t)HD*HD];                            // Wk^T s=6
__device__ h16  g_wvth[(size_t)HD*HD];                            // Wv^T s=6
__device__ h16  g_woh[(size_t)HD*HD];                             // Wo   s=6
__device__ h16  g_w1h[(size_t)HD*HD];                             // W1   s=6
__device__ h16  g_wqkth[(size_t)HD*HD];                           // (Wq^T Wk)^T s=6
__device__ h16  g_m1th[(size_t)HD*HD];                            // (Wo Wv)^T   s=6
__device__ h16  g_wvfh[(size_t)HD*HD];                            // W1WoWv s=7
__device__ h16  g_th[(size_t)TOK*HD];                             // t s=1
__device__ h16  g_uth[(size_t)TOK*HD];                            // u^T s=2
__device__ h16  g_sch[(size_t)NB*SEQ*SEQ];                        // logits fp16
__device__ h16  g_ph[(size_t)NB*SEQ*SEQ];                         // P s=0
__device__ float g_w2s[HD];
__device__ double g_acc;

// ---------------- helpers -----------------------------------------------------
__device__ __forceinline__ uint32_t s2u(const void* p){
    uint32_t a;
    asm("{ .reg .u64 t; cvta.to.shared.u64 t, %1; cvt.u32.u64 %0, t; }" : "=r"(a) : "l"(p));
    return a;
}
__device__ __forceinline__ uint32_t pkh(h16 a, h16 b){
    __half2 t(a, b); return *reinterpret_cast<uint32_t*>(&t);
}

#define CPA(dst, src) asm volatile("cp.async.cg.shared.global [%0], [%1], 16;" \
    :: "r"(dst), "l"(src) : "memory")
#define CPA_COMMIT() asm volatile("cp.async.commit_group;" ::: "memory")

__device__ __forceinline__ void ldm4(uint32_t* r, uint32_t addr){
    asm volatile("ldmatrix.sync.aligned.m8n8.x4.shared.b16 {%0,%1,%2,%3}, [%4];"
        : "=r"(r[0]), "=r"(r[1]), "=r"(r[2]), "=r"(r[3]) : "r"(addr));
}
__device__ __forceinline__ void mma_f16(float* d, const uint32_t* a, const uint32_t* b){
    asm volatile(
        "mma.sync.aligned.m16n8k16.row.col.f32.f16.f16.f32 "
        "{%0,%1,%2,%3}, {%4,%5,%6,%7}, {%8,%9}, {%0,%1,%2,%3};"
        : "+f"(d[0]), "+f"(d[1]), "+f"(d[2]), "+f"(d[3])
        : "r"(a[0]), "r"(a[1]), "r"(a[2]), "r"(a[3]), "r"(b[0]), "r"(b[1]));
}

#define TILE_B   16384
#define STAGE_B  32768
#define NSTAGE   3
#define SMEM_TOT (NSTAGE*STAGE_B)    // 96KB -> 2 CTAs/SM

// ---------------- 1-term fp16 GEMM device body ---------------------------------
// C[m,n] = oscale * sum_k A[m,k]*B[n,k]  (NT), K=2048, leading dims 2048.
// 128 threads, 2x2 warps of 64x64 tiles. Caller pre-offsets pointers per batch.
// MODE 0: write fp16 Ch ; 2: sum(relu(C)*w2s) -> g_acc
// Mainloop order (R14-proven): wait_group -> __syncthreads -> produce -> consume.
// The barrier AFTER the wait is what makes other threads' cp.async completions
// visible to this thread's ldmatrix — do not reorder (R15 bug).
template<int MODE>
__device__ __forceinline__ void gemm_body(
    const h16* __restrict__ Ah, const h16* __restrict__ Bh,
    h16* __restrict__ Ch,
    const float* __restrict__ w2s, float oscale,
    int bm, int bn, char* smem)
{
    const uint32_t sb = s2u(smem);

    const int tid = threadIdx.x;
    const int l   = tid & 31;
    const int wid = tid >> 5;         // 0..3
    const int wm  = wid & 1;          // 2 warps along M (64 rows each)
    const int wn  = wid >> 1;         // 2 warps along N (64 cols each)

    // ---- producer (cp.async) addressing: 128 threads cover 16 rows x 128B
    const int pr = tid >> 3;                 // 0..15 base row
    const int pc = (tid & 7) * 16;           // byte col in 128B row
    const uint32_t pdst = (uint32_t)pr * 128u + ((uint32_t)pc ^ (((uint32_t)pr & 7u) << 4));
    const char* gAh = (const char*)(Ah + (size_t)(bm + pr) * KDIM) + pc;
    const char* gBh = (const char*)(Bh + (size_t)(bn + pr) * KDIM) + pc;

    // ---- consumer (ldmatrix) addressing
    const int ar    = wm * 64 + (l & 15);
    const int akoff = (l >> 4) * 16;
    const uint32_t xA = ((uint32_t)ar & 7u) << 4;
    const int br    = wn * 64 + (l & 7) + ((l >> 4) & 1) * 8;   // + p*16
    const int bkoff = ((l >> 3) & 1) * 16;
    const uint32_t xB = ((uint32_t)br & 7u) << 4;

    float acc[4][8][4];
    #pragma unroll
    for (int i = 0; i < 4; i++)
        #pragma unroll
        for (int j = 0; j < 8; j++)
            #pragma unroll
            for (int r = 0; r < 4; r++) acc[i][j][r] = 0.f;

    // ---- prologue: chunks 0,1 into bufs 0,1 (8 row-strides of 16 rows each)
    #pragma unroll
    for (int s = 0; s < NSTAGE - 1; s++){
        const uint32_t s0 = sb + (uint32_t)s * STAGE_B;
        const size_t ko = (size_t)s * 128;
        #pragma unroll
        for (int j = 0; j < 8; j++){
            const size_t go = (size_t)j * 65536 + ko;     // +16 rows
            CPA(s0 +          pdst + j*2048, gAh + go);
            CPA(s0 + TILE_B + pdst + j*2048, gBh + go);
        }
        CPA_COMMIT();
    }

    int bufc = 0;
    int bufp = NSTAGE - 1;
    #pragma unroll 1
    for (int i = 0; i < KITERS; i++){
        asm volatile("cp.async.wait_group 1;" ::: "memory");
        __syncthreads();

        // produce chunk i+2 into the just-freed buffer (after sync => safe)
        if (i + NSTAGE - 1 < KITERS){
            const uint32_t s0 = sb + (uint32_t)bufp * STAGE_B;
            const size_t ko = (size_t)(i + NSTAGE - 1) * 128;
            #pragma unroll
            for (int j = 0; j < 8; j++){
                const size_t go = (size_t)j * 65536 + ko;
                CPA(s0 +          pdst + j*2048, gAh + go);
                CPA(s0 + TILE_B + pdst + j*2048, gBh + go);
            }
        }
        CPA_COMMIT();   // always commit to keep group counting aligned

        const uint32_t s0 = sb + (uint32_t)bufc * STAGE_B;
        #pragma unroll
        for (int ks = 0; ks < 4; ks++){
            const uint32_t kb = (uint32_t)ks * 32;
            uint32_t ah[4][4];
            #pragma unroll
            for (int fm = 0; fm < 4; fm++){
                uint32_t ad = s0 + (uint32_t)(ar + fm*16) * 128u + ((kb + akoff) ^ xA);
                ldm4(ah[fm], ad);
            }
            #pragma unroll
            for (int p = 0; p < 4; p++){          // stream B: 16 N-rows -> 2 fn
                uint32_t bh[4];
                uint32_t bd = s0 + TILE_B + (uint32_t)(br + p*16) * 128u + ((kb + bkoff) ^ xB);
                ldm4(bh, bd);
                #pragma unroll
                for (int fm = 0; fm < 4; fm++){
                    mma_f16(acc[fm][2*p + 0], ah[fm], &bh[0]);
                    mma_f16(acc[fm][2*p + 1], ah[fm], &bh[2]);
                }
            }
        }

        bufc = (bufc + 1 == NSTAGE) ? 0 : bufc + 1;
        bufp = (bufp + 1 == NSTAGE) ? 0 : bufp + 1;
    }

    // ---- epilogue
    const int crow = l >> 2;
    const int ccol = (l & 3) * 2;
    double local = 0.0;

    #pragma unroll
    for (int fm = 0; fm < 4; fm++){
        #pragma unroll
        for (int fn = 0; fn < 8; fn++){
            const int m0 = bm + wm*64 + fm*16 + crow;
            const int n0 = bn + wn*64 + fn*8 + ccol;
            const float* c = acc[fm][fn];
            if (MODE == 0){
                const size_t o0 = (size_t)m0 * KDIM + n0;
                const size_t o1 = (size_t)(m0+8) * KDIM + n0;
                *(uint32_t*)(Ch + o0) = pkh(__float2half_rn(c[0]*oscale),
                                            __float2half_rn(c[1]*oscale));
                *(uint32_t*)(Ch + o1) = pkh(__float2half_rn(c[2]*oscale),
                                            __float2half_rn(c[3]*oscale));
            } else {
                float w0 = w2s[n0], w1 = w2s[n0+1];
                float z;
                z = c[0]*oscale; local += (double)((z > 0.f ? z : 0.f) * w0);
                z = c[1]*oscale; local += (double)((z > 0.f ? z : 0.f) * w1);
                z = c[2]*oscale; local += (double)((z > 0.f ? z : 0.f) * w0);
                z = c[3]*oscale; local += (double)((z > 0.f ? z : 0.f) * w1);
            }
        }
    }

    if (MODE == 2){
        __syncthreads();
        double* red = (double*)smem;
        red[tid] = local;
        __syncthreads();
        #pragma unroll
        for (int s = 64; s > 0; s >>= 1){
            if (tid < s) red[tid] += red[tid + s];
            __syncthreads();
        }
        if (tid == 0) atomicAdd(&g_acc, red[0]);
    }
}

// ---------------- GEMM kernels --------------------------------------------------
// batched (z) GEMM with per-batch strides
template<int MODE>
__global__ void __launch_bounds__(NTHREADS, 2) mma_one(
    const h16* __restrict__ Ah, const h16* __restrict__ Bh,
    h16* __restrict__ Ch, const float* __restrict__ w2s, float oscale,
    size_t sA, size_t sB, size_t sC)
{
    extern __shared__ char smem[];
    const size_t zo = blockIdx.z;
    gemm_body<MODE>(Ah + zo*sA, Bh + zo*sB,
                    (MODE == 0) ? Ch + zo*sC : nullptr,
                    w2s, oscale, blockIdx.y * BM, blockIdx.x * BN, smem);
}

// launch1: z=0 -> Wqkt = NT(Wk^T, Wq^T) ; z=1 -> M1t = NT(Wv^T, Wo) ; both os 2^-6
__global__ void __launch_bounds__(NTHREADS, 2) k_wqkt_m1t(
    const h16* __restrict__ wkth, const h16* __restrict__ wqth, h16* __restrict__ wqkth,
    const h16* __restrict__ wvth, const h16* __restrict__ woh,  h16* __restrict__ m1th)
{
    extern __shared__ char smem[];
    const h16 *A, *B; h16* C;
    if (blockIdx.z == 0){ A = wkth; B = wqth; C = wqkth; }
    else                { A = wvth; B = woh;  C = m1th;  }
    gemm_body<0>(A, B, C, nullptr, 0.015625f, blockIdx.y * BM, blockIdx.x * BN, smem);
}

// launch2: y<16 -> Wvf = NT(W1, M1t) ; y>=16 -> t = NT(x, Wqkt) ; both os 2^-5
__global__ void __launch_bounds__(NTHREADS, 2) k_wvf_t(
    const h16* __restrict__ w1h, const h16* __restrict__ m1th, h16* __restrict__ wvfh,
    const h16* __restrict__ xh,  const h16* __restrict__ wqkth, h16* __restrict__ th)
{
    extern __shared__ char smem[];
    const int y = blockIdx.y;
    const h16 *A, *B; h16* C; int bm;
    if (y < 16){ A = w1h; B = m1th;  C = wvfh; bm = y * BM; }
    else       { A = xh;  B = wqkth; C = th;   bm = (y - 16) * BM; }
    gemm_body<0>(A, B, C, nullptr, 0.03125f, bm, blockIdx.x * BN, smem);
}

// launch3: y<64 -> score[b] = NT(t[b], x[b]) os 0.5 ; y>=64 -> uT[b] = NT(Wvf, x[b]) os 2^-5
__global__ void __launch_bounds__(NTHREADS, 2) k_score_ut(
    const h16* __restrict__ th, const h16* __restrict__ xh, h16* __restrict__ sch,
    const h16* __restrict__ wvfh, h16* __restrict__ uth)
{
    extern __shared__ char smem[];
    const size_t SH = (size_t)SEQ * HD;
    const size_t SS = (size_t)SEQ * SEQ;
    const int y = blockIdx.y;
    const h16 *A, *B; h16* C; int bm; float os;
    if (y < 64){            // score, batch b
        const int b = y >> 4;
        A = th + (size_t)b * SH;  B = xh + (size_t)b * SH;  C = sch + (size_t)b * SS;
        bm = (y & 15) * BM;  os = 0.5f;
    } else {                // uT, batch b
        const int yy = y - 64;
        const int b  = yy >> 4;
        A = wvfh;  B = xh + (size_t)b * SH;  C = uth + (size_t)b * SH;
        bm = (yy & 15) * BM;  os = 0.03125f;
    }
    gemm_body<0>(A, B, C, nullptr, os, bm, blockIdx.x * BN, smem);
}

// ---------------- aux kernels -------------------------------------------------
__global__ void chalf_k(const float4* __restrict__ in, uint2* __restrict__ oh,
                        float scale)
{
    size_t i = (size_t)blockIdx.x * 256 + threadIdx.x;
    float4 f = in[i];
    oh[i] = make_uint2(pkh(__float2half_rn(f.x*scale), __float2half_rn(f.y*scale)),
                       pkh(__float2half_rn(f.z*scale), __float2half_rn(f.w*scale)));
}

// merged weight chalf: z selects (Wo, W1)
__global__ void chalf2_k(const float4* __restrict__ w0, uint2* __restrict__ o0,
                         const float4* __restrict__ w1, uint2* __restrict__ o1,
                         float scale)
{
    size_t i = (size_t)blockIdx.x * 256 + threadIdx.x;
    const float4* in = (blockIdx.z == 0) ? w0 : w1;
    uint2* oh        = (blockIdx.z == 0) ? o0 : o1;
    float4 f = in[i];
    oh[i] = make_uint2(pkh(__float2half_rn(f.x*scale), __float2half_rn(f.y*scale)),
                       pkh(__float2half_rn(f.z*scale), __float2half_rn(f.w*scale)));
}

// merged transpose: out[C][R] = in[R][C] * scale ; z selects (Wq, Wk, Wv)
__global__ void thalf3_k(const float* __restrict__ i0, h16* __restrict__ o0,
                         const float* __restrict__ i1, h16* __restrict__ o1,
                         const float* __restrict__ i2, h16* __restrict__ o2,
                         float scale)
{
    __shared__ float t[32][33];
    const float* in = (blockIdx.z == 0) ? i0 : (blockIdx.z == 1) ? i1 : i2;
    h16* oh         = (blockIdx.z == 0) ? o0 : (blockIdx.z == 1) ? o1 : o2;
    int c0 = blockIdx.x * 32, r0 = blockIdx.y * 32;
    int tx = threadIdx.x, ty = threadIdx.y;
    #pragma unroll
    for (int j = 0; j < 32; j += 8)
        t[ty + j][tx] = in[(size_t)(r0 + ty + j) * HD + c0 + tx];
    __syncthreads();
    #pragma unroll
    for (int j = 0; j < 32; j += 8){
        size_t o = (size_t)(c0 + ty + j) * HD + r0 + tx;
        oh[o] = __float2half_rn(t[tx][ty + j] * scale);
    }
}

// row softmax over fp16 logits -> fp16 probs; 256 threads, 8 halves/thread
__global__ void softmax_k(const h16* __restrict__ S, h16* __restrict__ Ph)
{
    const size_t ro = (size_t)blockIdx.x * SEQ;
    const uint4* rin = (const uint4*)(S + ro);
    uint4* rout      = (uint4*)(Ph + ro);
    const int tid = threadIdx.x;  // 256
    __shared__ float sm[256];

    uint4 raw = rin[tid];
    const __half2* hp = (const __half2*)&raw;
    float v[8];
    #pragma unroll
    for (int t = 0; t < 4; t++){
        float2 f = __half22float2(hp[t]);
        v[2*t] = f.x;  v[2*t+1] = f.y;
    }

    float mx = -3.0e38f;
    #pragma unroll
    for (int t = 0; t < 8; t++) mx = fmaxf(mx, v[t]);
    sm[tid] = mx; __syncthreads();
    #pragma unroll
    for (int s = 128; s > 0; s >>= 1){
        if (tid < s) sm[tid] = fmaxf(sm[tid], sm[tid + s]);
        __syncthreads();
    }
    mx = sm[0]; __syncthreads();

    float sum = 0.f;
    #pragma unroll
    for (int t = 0; t < 8; t++){ v[t] = expf(v[t] - mx); sum += v[t]; }
    sm[tid] = sum; __syncthreads();
    #pragma unroll
    for (int s = 128; s > 0; s >>= 1){
        if (tid < s) sm[tid] += sm[tid + s];
        __syncthreads();
    }
    float inv = 1.0f / sm[0];

    uint4 out;
    __half2* op = (__half2*)&out;
    #pragma unroll
    for (int t = 0; t < 4; t++)
        op[t] = __floats2half2_rn(v[2*t] * inv, v[2*t+1] * inv);
    rout[tid] = out;
}

// parallel deterministic column sum: w2s[e] = sum_d W2[d][e]
// 64 blocks x 256 threads; block b owns cols [b*32, b*32+32), 8 row-groups of 256
__global__ void w2sum_k(const float* __restrict__ W2)
{
    __shared__ float sm[8][32];
    const int c = threadIdx.x & 31;
    const int g = threadIdx.x >> 5;          // 0..7
    const int e = blockIdx.x * 32 + c;
    if (blockIdx.x == 0 && threadIdx.x == 0) g_acc = 0.0;

    const float* p = W2 + (size_t)(g * 256) * HD + e;
    float s = 0.f;
    #pragma unroll 8
    for (int d = 0; d < 256; d++)
        s += p[(size_t)d * HD];
    sm[g][c] = s;
    __syncthreads();

    if (g == 0){
        float t = 0.f;
        #pragma unroll
        for (int k = 0; k < 8; k++) t += sm[k][c];   // fixed order -> deterministic
        g_w2s[e] = t;
    }
}

__global__ void out_k(float* __restrict__ out){ out[0] = (float)g_acc; }

// ---------------- launch --------------------------------------------------------
extern "C" void kernel_launch(void* const* d_in, const int* in_sizes, int n_in,
                              void* d_out, int out_size)
{
    const float* x  = (const float*)d_in[0];
    const float* Wq = (const float*)d_in[1];
    const float* Wk = (const float*)d_in[2];
    const float* Wv = (const float*)d_in[3];
    const float* Wo = (const float*)d_in[4];
    const float* W1 = (const float*)d_in[5];
    const float* W2 = (const float*)d_in[6];

    cudaFuncSetAttribute(mma_one<2>,  cudaFuncAttributeMaxDynamicSharedMemorySize, SMEM_TOT);
    cudaFuncSetAttribute(k_wqkt_m1t,  cudaFuncAttributeMaxDynamicSharedMemorySize, SMEM_TOT);
    cudaFuncSetAttribute(k_wvf_t,     cudaFuncAttributeMaxDynamicSharedMemorySize, SMEM_TOT);
    cudaFuncSetAttribute(k_score_ut,  cudaFuncAttributeMaxDynamicSharedMemorySize, SMEM_TOT);

    h16 *xh,*wqth,*wkth,*wvth,*woh,*w1h,*wqkth,*m1th,*wvfh,*th,*uth,*sch,*ph;
    float *w2s;
    cudaGetSymbolAddress((void**)&xh, g_xh);
    cudaGetSymbolAddress((void**)&wqth, g_wqth);
    cudaGetSymbolAddress((void**)&wkth, g_wkth);
    cudaGetSymbolAddress((void**)&wvth, g_wvth);
    cudaGetSymbolAddress((void**)&woh, g_woh);
    cudaGetSymbolAddress((void**)&w1h, g_w1h);
    cudaGetSymbolAddress((void**)&wqkth, g_wqkth);
    cudaGetSymbolAddress((void**)&m1th, g_m1th);
    cudaGetSymbolAddress((void**)&wvfh, g_wvfh);
    cudaGetSymbolAddress((void**)&th, g_th);
    cudaGetSymbolAddress((void**)&uth, g_uth);
    cudaGetSymbolAddress((void**)&sch, g_sch);
    cudaGetSymbolAddress((void**)&ph, g_ph);
    cudaGetSymbolAddress((void**)&w2s, g_w2s);

    const size_t SH = (size_t)SEQ * HD;
    const size_t SS = (size_t)SEQ * SEQ;
    const float WS = 64.0f;           // weight pre-scale 2^6

    w2sum_k<<<HD/32, 256>>>(W2);

    // inputs -> fp16 hi-only (scaled)
    chalf_k<<<(int)((size_t)TOK*HD/1024), 256>>>((const float4*)x, (uint2*)xh, 1.0f);
    chalf2_k<<<dim3(HD*HD/1024, 1, 2), 256>>>((const float4*)Wo, (uint2*)woh,
                                              (const float4*)W1, (uint2*)w1h, WS);
    thalf3_k<<<dim3(HD/32, HD/32, 3), dim3(32, 8)>>>(Wq, wqth, Wk, wkth, Wv, wvth, WS);

    // L1: Wqkt = NT(Wk^T, Wq^T) ; M1t = NT(Wv^T, Wo)   (both s=6, os=2^-6)
    k_wqkt_m1t<<<dim3(16, 16, 2), NTHREADS, SMEM_TOT>>>(wkth, wqth, wqkth,
                                                        wvth, woh, m1th);
    // L2: Wvf = NT(W1, M1t) s=7 ; t = NT(x, Wqkt) s=1   (both os=2^-5)
    k_wvf_t<<<dim3(16, 80, 1), NTHREADS, SMEM_TOT>>>(w1h, m1th, wvfh, xh, wqkth, th);
    // L3: score[b] = NT(t[b], x[b]) fp16 os=0.5 ; uT[b] = NT(Wvf, x[b]) s=2 os=2^-5
    k_score_ut<<<dim3(16, 128, 1), NTHREADS, SMEM_TOT>>>(th, xh, sch, wvfh, uth);

    softmax_k<<<NB*SEQ, 256>>>(sch, ph);

    // Z[b] = NT(P[b], uT[b]) reduce; os=2^(0-0-2)
    mma_one<2><<<dim3(16, 16, NB), NTHREADS, SMEM_TOT>>>(ph, uth, nullptr, w2s,
                                                         0.25f, SS, SH, 0);

    out_k<<<1,1>>>((float*)d_out);
}